// round 10
// baseline (speedup 1.0000x reference)
#include <cuda_runtime.h>
#include <math.h>

#define BB 4
#define NN 512
#define HH 64
#define NH 4
#define DD 16
#define SCALE 0.25f      // 1/sqrt(16)
#define LN_EPS 1e-5f
#define TI 8             // query rows per attn block

// Scratch (allocation-free: __device__ globals)
__device__ float g_T [BB*NN*HH];
__device__ float g_Q [BB*NN*HH];
__device__ float g_Kt[BB*HH*NN];   // K transposed: [b][hd][j]
__device__ float g_V [BB*NN*HH];
__device__ float g_qw5[BB*NN*NH];
__device__ float g_qb5[BB*NN*NH];

// ---------------------------------------------------------------------------
// Kernel 1: node projections. 256 threads = 4 groups x 64; each group does
// 8 rows (one thread per out column). K written transposed.
// ---------------------------------------------------------------------------
__global__ __launch_bounds__(256)
void proj_kernel(const float* __restrict__ x,
    const float* __restrict__ W1w, const float* __restrict__ W1b,
    const float* __restrict__ W2w, const float* __restrict__ W2b,
    const float* __restrict__ W3w, const float* __restrict__ W3b,
    const float* __restrict__ W4w, const float* __restrict__ W4b,
    const float* __restrict__ W5w, const float* __restrict__ W5b)
{
    const int g = threadIdx.x >> 6;        // group 0..3
    const int t = threadIdx.x & 63;        // out column
    const int row0 = blockIdx.x * 32 + g * 8;

    __shared__ float sx[4][8][64];
    __shared__ float sq[4][8][64];

    #pragma unroll
    for (int r = 0; r < 8; r++) sx[g][r][t] = x[(row0 + r)*HH + t];
    __syncthreads();

    float a1[8], a2[8], a3[8], a4[8];
    #pragma unroll
    for (int r = 0; r < 8; r++) { a1[r]=0.f; a2[r]=0.f; a3[r]=0.f; a4[r]=0.f; }

    #pragma unroll 8
    for (int k = 0; k < 64; k++) {
        const float w1 = W1w[k*64 + t];
        const float w2 = W2w[k*64 + t];
        const float w3 = W3w[k*64 + t];
        const float w4 = W4w[k*64 + t];
        #pragma unroll
        for (int r = 0; r < 8; r++) {
            const float xk = sx[g][r][k];
            a1[r] = fmaf(xk, w1, a1[r]);
            a2[r] = fmaf(xk, w2, a2[r]);
            a3[r] = fmaf(xk, w3, a3[r]);
            a4[r] = fmaf(xk, w4, a4[r]);
        }
    }

    const float b1 = W1b[t], b2 = W2b[t], b3 = W3b[t], b4 = W4b[t];
    #pragma unroll
    for (int r = 0; r < 8; r++) {
        const float q = a3[r] + b3;
        g_T[(row0 + r)*HH + t] = a1[r] + b1;
        g_V[(row0 + r)*HH + t] = a2[r] + b2;
        g_Q[(row0 + r)*HH + t] = q;
        sq[g][r][t] = q;
    }

    // K transposed: thread owns column t, nodes n0..n0+7 (contiguous in Kt)
    {
        const int bq = row0 >> 9;          // / NN
        const int n0 = row0 & (NN - 1);
        float* kt = &g_Kt[((long)bq*HH + t)*NN + n0];
        *(float4*)(kt)     = make_float4(a4[0]+b4, a4[1]+b4, a4[2]+b4, a4[3]+b4);
        *(float4*)(kt + 4) = make_float4(a4[4]+b4, a4[5]+b4, a4[6]+b4, a4[7]+b4);
    }
    __syncthreads();

    // qw5/qb5: edge-term scalars per (row, head)
    if (t < 32) {
        const int r = t >> 2, h = t & 3;
        float sw = 0.f, sb = 0.f;
        #pragma unroll
        for (int d = 0; d < 16; d++) {
            const float q = sq[g][r][h*16 + d];
            sw = fmaf(q, W5w[h*16 + d], sw);
            sb = fmaf(q, W5b[h*16 + d], sb);
        }
        g_qw5[(row0 + r)*NH + h] = sw;
        g_qb5[(row0 + r)*NH + h] = sb;
    }
}

// ---------------------------------------------------------------------------
// Kernel 2: fused scores+exp + sum + attn*V(normalized) + residual + LN.
// One block per (b, TI=8 query rows). 512 threads. Dynamic smem (~86 KB).
// No max-subtraction in softmax: scores have |.| <~ 3 by construction, and
// masked entries store exp = 0 exactly.
// ---------------------------------------------------------------------------
#define SM_FLOATS (TI*NH*NN + HH*TI + TI*NH + TI*NH + 32 + 8*TI*HH + TI*HH)
#define SM_BYTES  (SM_FLOATS * 4)

__global__ __launch_bounds__(512)
void attn_kernel(const float* __restrict__ x,
                 const int*   __restrict__ adj,
                 const float* __restrict__ ef,
                 const float* __restrict__ lng,
                 const float* __restrict__ lnb,
                 float* __restrict__ out)
{
    extern __shared__ float smem[];
    float* s_sc  = smem;                   // [TI*NH][NN] exp(scores)
    float* s_qt  = s_sc + TI*NH*NN;        // [HH][TI]  Q transposed
    float* s_qw  = s_qt + HH*TI;           // TI*NH
    float* s_qb  = s_qw + TI*NH;           // TI*NH
    float* s_inv = s_qb + TI*NH;           // 32: 1/sum per unit
    float* s_red = s_inv + 32;             // [8][TI*HH]
    float* s_y   = s_red + 8*TI*HH;        // TI*HH

    const int tid = threadIdx.x;                  // 0..511
    const int b   = blockIdx.x / (NN / TI);
    const int i0  = (blockIdx.x % (NN / TI)) * TI;

    // Stage Q transposed: s_qt[hd][i]
    {
        const int i = tid >> 6, hd = tid & 63;
        s_qt[hd*TI + i] = g_Q[(b*NN + i0 + i)*HH + hd];
    }
    if (tid < TI*NH) {
        s_qw[tid] = g_qw5[(b*NN + i0)*NH + tid];
        s_qb[tid] = g_qb5[(b*NN + i0)*NH + tid];
    }
    __syncthreads();

    // ---- Phase 1: scores + exp. thread j streams Kt coalesced. ----
    {
        const int j = tid;
        const float* KtB = &g_Kt[(long)b*HH*NN];
        float ev[TI]; int av[TI];
        #pragma unroll
        for (int i = 0; i < TI; i++) {
            const long base = (long)(b*NN + i0 + i)*NN + j;
            ev[i] = ef[base];
            av[i] = adj[base];
        }
        float acc[NH][TI];
        #pragma unroll
        for (int h = 0; h < NH; h++)
            #pragma unroll
            for (int i = 0; i < TI; i++) acc[h][i] = 0.f;

        #pragma unroll
        for (int h = 0; h < NH; h++) {
            #pragma unroll
            for (int d = 0; d < DD; d++) {
                const int hd = h*DD + d;
                const float kt = KtB[hd*NN + j];           // coalesced LDG
                const float4 qa = *(const float4*)&s_qt[hd*TI];     // broadcast
                const float4 qb = *(const float4*)&s_qt[hd*TI + 4];
                acc[h][0] = fmaf(qa.x, kt, acc[h][0]);
                acc[h][1] = fmaf(qa.y, kt, acc[h][1]);
                acc[h][2] = fmaf(qa.z, kt, acc[h][2]);
                acc[h][3] = fmaf(qa.w, kt, acc[h][3]);
                acc[h][4] = fmaf(qb.x, kt, acc[h][4]);
                acc[h][5] = fmaf(qb.y, kt, acc[h][5]);
                acc[h][6] = fmaf(qb.z, kt, acc[h][6]);
                acc[h][7] = fmaf(qb.w, kt, acc[h][7]);
            }
        }
        #pragma unroll
        for (int i = 0; i < TI; i++)
            #pragma unroll
            for (int h = 0; h < NH; h++) {
                const float e = av[i]
                    ? __expf((acc[h][i] + ev[i]*s_qw[i*NH + h]
                              + s_qb[i*NH + h]) * SCALE)
                    : 0.f;
                s_sc[(i*NH + h)*NN + j] = e;
            }
    }
    __syncthreads();

    // ---- Phase 2: per-unit sum -> 1/sum. warp w does units w, w+16. ----
    {
        const int w = tid >> 5, lane = tid & 31;
        #pragma unroll
        for (int uu = 0; uu < 2; uu++) {
            const int u = w + 16*uu;
            const float* row = &s_sc[u*NN];
            float sum = 0.f;
            #pragma unroll
            for (int k = 0; k < 16; k++) sum += row[lane + 32*k];
            #pragma unroll
            for (int o = 16; o; o >>= 1) sum += __shfl_xor_sync(0xffffffffu, sum, o);
            if (lane == 0) s_inv[u] = 1.f / sum;
        }
    }
    __syncthreads();

    // ---- Phase 3: msg = (E @ V) * inv. thread = (slice of j, col c). ----
    {
        const int slice = tid >> 6;   // 0..7
        const int c     = tid & 63;   // h*16+d
        const int h     = c >> 4;
        float acc[TI];
        #pragma unroll
        for (int i = 0; i < TI; i++) acc[i] = 0.f;
        const float* Vb = &g_V[(long)b*NN*HH];
        #pragma unroll
        for (int js = 0; js < 16; js++) {
            const int jx = slice*64 + js*4;
            const float v0 = Vb[(jx+0)*HH + c];
            const float v1 = Vb[(jx+1)*HH + c];
            const float v2 = Vb[(jx+2)*HH + c];
            const float v3 = Vb[(jx+3)*HH + c];
            #pragma unroll
            for (int i = 0; i < TI; i++) {
                const float4 p = *(const float4*)&s_sc[(i*NH + h)*NN + jx];
                acc[i] = fmaf(p.x, v0, acc[i]);
                acc[i] = fmaf(p.y, v1, acc[i]);
                acc[i] = fmaf(p.z, v2, acc[i]);
                acc[i] = fmaf(p.w, v3, acc[i]);
            }
        }
        #pragma unroll
        for (int i = 0; i < TI; i++)
            s_red[(slice*TI + i)*HH + c] = acc[i] * s_inv[i*NH + h];
    }
    __syncthreads();

    // ---- Phase 3b: reduce slices + residual. tid covers TI*HH = 512. ----
    {
        const int i = tid >> 6, c = tid & 63;
        float m = 0.f;
        #pragma unroll
        for (int s = 0; s < 8; s++) m += s_red[(s*TI + i)*HH + c];
        const long r = (long)(b*NN + i0 + i)*HH + c;
        s_y[i*HH + c] = x[r] + g_T[r] + m;
    }
    __syncthreads();

    // ---- Phase 4: LayerNorm. warp w handles row i=w (TI*32 = 256 threads). -
    if (tid < TI*32) {
        const int i = tid >> 5, l = tid & 31;
        const float y0 = s_y[i*HH + l];
        const float y1 = s_y[i*HH + l + 32];
        float s  = y0 + y1;
        float sq = y0*y0 + y1*y1;
        #pragma unroll
        for (int o = 16; o; o >>= 1) {
            s  += __shfl_xor_sync(0xffffffffu, s,  o);
            sq += __shfl_xor_sync(0xffffffffu, sq, o);
        }
        const float mean = s * (1.f/64.f);
        const float var  = sq * (1.f/64.f) - mean*mean;
        const float rs   = rsqrtf(var + LN_EPS);
        float* op = &out[(long)(b*NN + i0 + i)*HH];
        op[l]      = (y0 - mean)*rs*lng[l]      + lnb[l];
        op[l + 32] = (y1 - mean)*rs*lng[l + 32] + lnb[l + 32];
    }
}

// ---------------------------------------------------------------------------
extern "C" void kernel_launch(void* const* d_in, const int* in_sizes, int n_in,
                              void* d_out, int out_size)
{
    const float* x   = (const float*)d_in[0];
    const int*   adj = (const int*)  d_in[1];
    const float* ef  = (const float*)d_in[2];
    const float* W1w = (const float*)d_in[3];
    const float* W1b = (const float*)d_in[4];
    const float* W2w = (const float*)d_in[5];
    const float* W2b = (const float*)d_in[6];
    const float* W3w = (const float*)d_in[7];
    const float* W3b = (const float*)d_in[8];
    const float* W4w = (const float*)d_in[9];
    const float* W4b = (const float*)d_in[10];
    const float* W5w = (const float*)d_in[11];
    const float* W5b = (const float*)d_in[12];
    const float* lng = (const float*)d_in[13];
    const float* lnb = (const float*)d_in[14];

    cudaFuncSetAttribute(attn_kernel,
                         cudaFuncAttributeMaxDynamicSharedMemorySize, SM_BYTES);

    proj_kernel<<<BB*NN/32, 256>>>(x, W1w, W1b, W2w, W2b, W3w, W3b,
                                   W4w, W4b, W5w, W5b);
    attn_kernel<<<BB*NN/TI, 512, SM_BYTES>>>(x, adj, ef, lng, lnb,
                                             (float*)d_out);
}

// round 11
// speedup vs baseline: 1.0713x; 1.0713x over previous
#include <cuda_runtime.h>
#include <math.h>

#define BB 4
#define NN 512
#define HH 64
#define NH 4
#define DD 16
#define SCALE 0.25f      // 1/sqrt(16)
#define LN_EPS 1e-5f
#define TI 8             // query rows per attn block

// Scratch (allocation-free: __device__ globals)
__device__ float g_T [BB*NN*HH];
__device__ float g_Q [BB*NN*HH];
__device__ float g_Kt[BB*HH*NN];   // K transposed: [b][hd][j]
__device__ float g_V [BB*NN*HH];
__device__ float g_qw5[BB*NN*NH];
__device__ float g_qb5[BB*NN*NH];

// ---------------------------------------------------------------------------
// Kernel 1: node projections. 256 threads = 4 groups x 64; each group does
// 8 rows (one thread per out column). K written transposed.
// ---------------------------------------------------------------------------
__global__ __launch_bounds__(256)
void proj_kernel(const float* __restrict__ x,
    const float* __restrict__ W1w, const float* __restrict__ W1b,
    const float* __restrict__ W2w, const float* __restrict__ W2b,
    const float* __restrict__ W3w, const float* __restrict__ W3b,
    const float* __restrict__ W4w, const float* __restrict__ W4b,
    const float* __restrict__ W5w, const float* __restrict__ W5b)
{
    const int g = threadIdx.x >> 6;        // group 0..3
    const int t = threadIdx.x & 63;        // out column
    const int row0 = blockIdx.x * 32 + g * 8;

    __shared__ float sx[4][8][64];
    __shared__ float sq[4][8][64];

    #pragma unroll
    for (int r = 0; r < 8; r++) sx[g][r][t] = x[(row0 + r)*HH + t];
    __syncthreads();

    float a1[8], a2[8], a3[8], a4[8];
    #pragma unroll
    for (int r = 0; r < 8; r++) { a1[r]=0.f; a2[r]=0.f; a3[r]=0.f; a4[r]=0.f; }

    #pragma unroll 8
    for (int k = 0; k < 64; k++) {
        const float w1 = W1w[k*64 + t];
        const float w2 = W2w[k*64 + t];
        const float w3 = W3w[k*64 + t];
        const float w4 = W4w[k*64 + t];
        #pragma unroll
        for (int r = 0; r < 8; r++) {
            const float xk = sx[g][r][k];
            a1[r] = fmaf(xk, w1, a1[r]);
            a2[r] = fmaf(xk, w2, a2[r]);
            a3[r] = fmaf(xk, w3, a3[r]);
            a4[r] = fmaf(xk, w4, a4[r]);
        }
    }

    const float b1 = W1b[t], b2 = W2b[t], b3 = W3b[t], b4 = W4b[t];
    #pragma unroll
    for (int r = 0; r < 8; r++) {
        const float q = a3[r] + b3;
        g_T[(row0 + r)*HH + t] = a1[r] + b1;
        g_V[(row0 + r)*HH + t] = a2[r] + b2;
        g_Q[(row0 + r)*HH + t] = q;
        sq[g][r][t] = q;
    }

    // K transposed: thread owns column t, nodes n0..n0+7 (contiguous in Kt)
    {
        const int bq = row0 >> 9;          // / NN
        const int n0 = row0 & (NN - 1);
        float* kt = &g_Kt[((long)bq*HH + t)*NN + n0];
        *(float4*)(kt)     = make_float4(a4[0]+b4, a4[1]+b4, a4[2]+b4, a4[3]+b4);
        *(float4*)(kt + 4) = make_float4(a4[4]+b4, a4[5]+b4, a4[6]+b4, a4[7]+b4);
    }
    __syncthreads();

    // qw5/qb5: edge-term scalars per (row, head)
    if (t < 32) {
        const int r = t >> 2, h = t & 3;
        float sw = 0.f, sb = 0.f;
        #pragma unroll
        for (int d = 0; d < 16; d++) {
            const float q = sq[g][r][h*16 + d];
            sw = fmaf(q, W5w[h*16 + d], sw);
            sb = fmaf(q, W5b[h*16 + d], sb);
        }
        g_qw5[(row0 + r)*NH + h] = sw;
        g_qb5[(row0 + r)*NH + h] = sb;
    }
}

// ---------------------------------------------------------------------------
// Kernel 2: fused scores+exp + sum + attn*V(normalized) + residual + LN.
// One block per (b, TI=8 query rows). 512 threads. Dynamic smem (~86 KB).
// launch_bounds(512,2) pins regs at 64 -> 2 blocks/SM (the R10 folded version
// hit 70 regs -> 1 block/SM -> occupancy collapse).
// ---------------------------------------------------------------------------
#define SM_FLOATS (TI*NH*NN + HH*TI + TI*NH + TI*NH + 32 + 8*TI*HH + TI*HH)
#define SM_BYTES  (SM_FLOATS * 4)

__global__ __launch_bounds__(512, 2)
void attn_kernel(const float* __restrict__ x,
                 const int*   __restrict__ adj,
                 const float* __restrict__ ef,
                 const float* __restrict__ lng,
                 const float* __restrict__ lnb,
                 float* __restrict__ out)
{
    extern __shared__ float smem[];
    float* s_sc  = smem;                   // [TI*NH][NN] exp(scores)
    float* s_qt  = s_sc + TI*NH*NN;        // [HH][TI]  Q transposed
    float* s_qw  = s_qt + HH*TI;           // TI*NH
    float* s_qb  = s_qw + TI*NH;           // TI*NH
    float* s_inv = s_qb + TI*NH;           // 32: 1/sum per unit
    float* s_red = s_inv + 32;             // [8][TI*HH]
    float* s_y   = s_red + 8*TI*HH;        // TI*HH

    const int tid = threadIdx.x;                  // 0..511
    const int b   = blockIdx.x / (NN / TI);
    const int i0  = (blockIdx.x % (NN / TI)) * TI;

    // Stage Q transposed: s_qt[hd][i]
    {
        const int i = tid >> 6, hd = tid & 63;
        s_qt[hd*TI + i] = g_Q[(b*NN + i0 + i)*HH + hd];
    }
    if (tid < TI*NH) {
        s_qw[tid] = g_qw5[(b*NN + i0)*NH + tid];
        s_qb[tid] = g_qb5[(b*NN + i0)*NH + tid];
    }
    __syncthreads();

    // ---- Phase 1: scores + exp. thread j streams Kt coalesced. ----
    {
        const int j = tid;
        const float* KtB = &g_Kt[(long)b*HH*NN];
        float ev[TI];
        unsigned int am = 0;     // adjacency bitmask (bit i)
        #pragma unroll
        for (int i = 0; i < TI; i++) {
            const long base = (long)(b*NN + i0 + i)*NN + j;
            ev[i] = ef[base];
            am |= (adj[base] ? 1u : 0u) << i;
        }
        float acc[NH][TI];
        #pragma unroll
        for (int h = 0; h < NH; h++)
            #pragma unroll
            for (int i = 0; i < TI; i++) acc[h][i] = 0.f;

        #pragma unroll
        for (int h = 0; h < NH; h++) {
            #pragma unroll
            for (int d = 0; d < DD; d++) {
                const int hd = h*DD + d;
                const float kt = KtB[hd*NN + j];           // coalesced LDG
                const float4 qa = *(const float4*)&s_qt[hd*TI];     // broadcast
                const float4 qb = *(const float4*)&s_qt[hd*TI + 4];
                acc[h][0] = fmaf(qa.x, kt, acc[h][0]);
                acc[h][1] = fmaf(qa.y, kt, acc[h][1]);
                acc[h][2] = fmaf(qa.z, kt, acc[h][2]);
                acc[h][3] = fmaf(qa.w, kt, acc[h][3]);
                acc[h][4] = fmaf(qb.x, kt, acc[h][4]);
                acc[h][5] = fmaf(qb.y, kt, acc[h][5]);
                acc[h][6] = fmaf(qb.z, kt, acc[h][6]);
                acc[h][7] = fmaf(qb.w, kt, acc[h][7]);
            }
        }
        #pragma unroll
        for (int i = 0; i < TI; i++) {
            const bool on = (am >> i) & 1u;
            #pragma unroll
            for (int h = 0; h < NH; h++) {
                const float e = on
                    ? __expf((acc[h][i] + ev[i]*s_qw[i*NH + h]
                              + s_qb[i*NH + h]) * SCALE)
                    : 0.f;
                s_sc[(i*NH + h)*NN + j] = e;
            }
        }
    }
    __syncthreads();

    // ---- Phase 2: per-unit sum -> 1/sum. warp w does units w, w+16. ----
    {
        const int w = tid >> 5, lane = tid & 31;
        #pragma unroll
        for (int uu = 0; uu < 2; uu++) {
            const int u = w + 16*uu;
            const float* row = &s_sc[u*NN];
            float sum = 0.f;
            #pragma unroll
            for (int k = 0; k < 16; k++) sum += row[lane + 32*k];
            #pragma unroll
            for (int o = 16; o; o >>= 1) sum += __shfl_xor_sync(0xffffffffu, sum, o);
            if (lane == 0) s_inv[u] = 1.f / sum;
        }
    }
    __syncthreads();

    // ---- Phase 3: msg = (E @ V) * inv. thread = (slice of j, col c). ----
    {
        const int slice = tid >> 6;   // 0..7
        const int c     = tid & 63;   // h*16+d
        const int h     = c >> 4;
        float acc[TI];
        #pragma unroll
        for (int i = 0; i < TI; i++) acc[i] = 0.f;
        const float* Vb = &g_V[(long)b*NN*HH];
        #pragma unroll
        for (int js = 0; js < 16; js++) {
            const int jx = slice*64 + js*4;
            const float v0 = Vb[(jx+0)*HH + c];
            const float v1 = Vb[(jx+1)*HH + c];
            const float v2 = Vb[(jx+2)*HH + c];
            const float v3 = Vb[(jx+3)*HH + c];
            #pragma unroll
            for (int i = 0; i < TI; i++) {
                const float4 p = *(const float4*)&s_sc[(i*NH + h)*NN + jx];
                acc[i] = fmaf(p.x, v0, acc[i]);
                acc[i] = fmaf(p.y, v1, acc[i]);
                acc[i] = fmaf(p.z, v2, acc[i]);
                acc[i] = fmaf(p.w, v3, acc[i]);
            }
        }
        #pragma unroll
        for (int i = 0; i < TI; i++)
            s_red[(slice*TI + i)*HH + c] = acc[i] * s_inv[i*NH + h];
    }
    __syncthreads();

    // ---- Phase 3b: reduce slices + residual. tid covers TI*HH = 512. ----
    {
        const int i = tid >> 6, c = tid & 63;
        float m = 0.f;
        #pragma unroll
        for (int s = 0; s < 8; s++) m += s_red[(s*TI + i)*HH + c];
        const long r = (long)(b*NN + i0 + i)*HH + c;
        s_y[i*HH + c] = x[r] + g_T[r] + m;
    }
    __syncthreads();

    // ---- Phase 4: LayerNorm. warp w handles row i=w (TI*32 = 256 threads). -
    if (tid < TI*32) {
        const int i = tid >> 5, l = tid & 31;
        const float y0 = s_y[i*HH + l];
        const float y1 = s_y[i*HH + l + 32];
        float s  = y0 + y1;
        float sq = y0*y0 + y1*y1;
        #pragma unroll
        for (int o = 16; o; o >>= 1) {
            s  += __shfl_xor_sync(0xffffffffu, s,  o);
            sq += __shfl_xor_sync(0xffffffffu, sq, o);
        }
        const float mean = s * (1.f/64.f);
        const float var  = sq * (1.f/64.f) - mean*mean;
        const float rs   = rsqrtf(var + LN_EPS);
        float* op = &out[(long)(b*NN + i0 + i)*HH];
        op[l]      = (y0 - mean)*rs*lng[l]      + lnb[l];
        op[l + 32] = (y1 - mean)*rs*lng[l + 32] + lnb[l + 32];
    }
}

// ---------------------------------------------------------------------------
extern "C" void kernel_launch(void* const* d_in, const int* in_sizes, int n_in,
                              void* d_out, int out_size)
{
    const float* x   = (const float*)d_in[0];
    const int*   adj = (const int*)  d_in[1];
    const float* ef  = (const float*)d_in[2];
    const float* W1w = (const float*)d_in[3];
    const float* W1b = (const float*)d_in[4];
    const float* W2w = (const float*)d_in[5];
    const float* W2b = (const float*)d_in[6];
    const float* W3w = (const float*)d_in[7];
    const float* W3b = (const float*)d_in[8];
    const float* W4w = (const float*)d_in[9];
    const float* W4b = (const float*)d_in[10];
    const float* W5w = (const float*)d_in[11];
    const float* W5b = (const float*)d_in[12];
    const float* lng = (const float*)d_in[13];
    const float* lnb = (const float*)d_in[14];

    cudaFuncSetAttribute(attn_kernel,
                         cudaFuncAttributeMaxDynamicSharedMemorySize, SM_BYTES);

    proj_kernel<<<BB*NN/32, 256>>>(x, W1w, W1b, W2w, W2b, W3w, W3b,
                                   W4w, W4b, W5w, W5b);
    attn_kernel<<<BB*NN/TI, 512, SM_BYTES>>>(x, adj, ef, lng, lnb,
                                             (float*)d_out);
}

// round 12
// speedup vs baseline: 1.1463x; 1.0700x over previous
#include <cuda_runtime.h>
#include <math.h>

#define BB 4
#define NN 512
#define HH 64
#define NH 4
#define DD 16
#define SCALE 0.25f      // 1/sqrt(16)
#define LN_EPS 1e-5f
#define TI 8             // query rows per attn block

// Scratch (allocation-free: __device__ globals)
__device__ float g_T [BB*NN*HH];
__device__ float g_Q [BB*NN*HH];
__device__ float g_Kt[BB*HH*NN];   // K transposed: [b][hd][j]
__device__ float g_V [BB*NN*HH];
__device__ float g_qw5[BB*NN*NH];
__device__ float g_qb5[BB*NN*NH];

// ---------------------------------------------------------------------------
// Kernel 1: node projections. 4 rows per block, 64 threads (one per out col),
// 512 blocks -> ~3.5 blocks/SM (the old 64-block shape left 84 SMs idle).
// K written transposed.
// ---------------------------------------------------------------------------
__global__ __launch_bounds__(64)
void proj_kernel(const float* __restrict__ x,
    const float* __restrict__ W1w, const float* __restrict__ W1b,
    const float* __restrict__ W2w, const float* __restrict__ W2b,
    const float* __restrict__ W3w, const float* __restrict__ W3b,
    const float* __restrict__ W4w, const float* __restrict__ W4b,
    const float* __restrict__ W5w, const float* __restrict__ W5b)
{
    const int t = threadIdx.x;          // 0..63 output column
    const int row0 = blockIdx.x * 4;    // global row index (b*N+n)

    __shared__ float sx[4][64];
    __shared__ float sq[4][64];

    #pragma unroll
    for (int r = 0; r < 4; r++) sx[r][t] = x[(row0 + r)*HH + t];
    __syncthreads();

    float a1[4], a2[4], a3[4], a4[4];
    #pragma unroll
    for (int r = 0; r < 4; r++) { a1[r]=0.f; a2[r]=0.f; a3[r]=0.f; a4[r]=0.f; }

    #pragma unroll 16
    for (int k = 0; k < 64; k++) {
        const float w1 = W1w[k*64 + t];
        const float w2 = W2w[k*64 + t];
        const float w3 = W3w[k*64 + t];
        const float w4 = W4w[k*64 + t];
        #pragma unroll
        for (int r = 0; r < 4; r++) {
            const float xk = sx[r][k];
            a1[r] = fmaf(xk, w1, a1[r]);
            a2[r] = fmaf(xk, w2, a2[r]);
            a3[r] = fmaf(xk, w3, a3[r]);
            a4[r] = fmaf(xk, w4, a4[r]);
        }
    }

    const float b1 = W1b[t], b2 = W2b[t], b3 = W3b[t], b4 = W4b[t];
    #pragma unroll
    for (int r = 0; r < 4; r++) {
        const float q = a3[r] + b3;
        g_T[(row0 + r)*HH + t] = a1[r] + b1;
        g_V[(row0 + r)*HH + t] = a2[r] + b2;
        g_Q[(row0 + r)*HH + t] = q;
        sq[r][t] = q;
    }

    // K transposed: thread owns column t, nodes n0..n0+3 (contiguous in Kt)
    {
        const int bq = row0 >> 9;          // / NN
        const int n0 = row0 & (NN - 1);
        float* kt = &g_Kt[((long)bq*HH + t)*NN + n0];
        *(float4*)(kt) = make_float4(a4[0]+b4, a4[1]+b4, a4[2]+b4, a4[3]+b4);
    }
    __syncthreads();

    // qw5/qb5: edge-term scalars per (row, head). 16 (r,h) pairs.
    if (t < 16) {
        const int r = t >> 2, h = t & 3;
        float sw = 0.f, sb = 0.f;
        #pragma unroll
        for (int d = 0; d < 16; d++) {
            const float q = sq[r][h*16 + d];
            sw = fmaf(q, W5w[h*16 + d], sw);
            sb = fmaf(q, W5b[h*16 + d], sb);
        }
        g_qw5[(row0 + r)*NH + h] = sw;
        g_qb5[(row0 + r)*NH + h] = sb;
    }
}

// ---------------------------------------------------------------------------
// Kernel 2: fused scores+exp + sum + attn*V(normalized) + residual + LN.
// One block per (b, TI=8 query rows). 512 threads. Dynamic smem (~86 KB).
// launch_bounds(512,2) pins regs at 64 -> 2 blocks/SM.
// ---------------------------------------------------------------------------
#define SM_FLOATS (TI*NH*NN + HH*TI + TI*NH + TI*NH + 32 + 8*TI*HH + TI*HH)
#define SM_BYTES  (SM_FLOATS * 4)

__global__ __launch_bounds__(512, 2)
void attn_kernel(const float* __restrict__ x,
                 const int*   __restrict__ adj,
                 const float* __restrict__ ef,
                 const float* __restrict__ lng,
                 const float* __restrict__ lnb,
                 float* __restrict__ out)
{
    extern __shared__ float smem[];
    float* s_sc  = smem;                   // [TI*NH][NN] exp(scores)
    float* s_qt  = s_sc + TI*NH*NN;        // [HH][TI]  Q transposed
    float* s_qw  = s_qt + HH*TI;           // TI*NH
    float* s_qb  = s_qw + TI*NH;           // TI*NH
    float* s_inv = s_qb + TI*NH;           // 32: 1/sum per unit
    float* s_red = s_inv + 32;             // [8][TI*HH]
    float* s_y   = s_red + 8*TI*HH;        // TI*HH

    const int tid = threadIdx.x;                  // 0..511
    const int b   = blockIdx.x / (NN / TI);
    const int i0  = (blockIdx.x % (NN / TI)) * TI;

    // Stage Q transposed: s_qt[hd][i]
    {
        const int i = tid >> 6, hd = tid & 63;
        s_qt[hd*TI + i] = g_Q[(b*NN + i0 + i)*HH + hd];
    }
    if (tid < TI*NH) {
        s_qw[tid] = g_qw5[(b*NN + i0)*NH + tid];
        s_qb[tid] = g_qb5[(b*NN + i0)*NH + tid];
    }
    __syncthreads();

    // ---- Phase 1: scores + exp. thread j streams Kt coalesced. ----
    {
        const int j = tid;
        const float* KtB = &g_Kt[(long)b*HH*NN];
        float ev[TI];
        unsigned int am = 0;     // adjacency bitmask (bit i)
        #pragma unroll
        for (int i = 0; i < TI; i++) {
            const long base = (long)(b*NN + i0 + i)*NN + j;
            ev[i] = ef[base];
            am |= (adj[base] ? 1u : 0u) << i;
        }
        float acc[NH][TI];
        #pragma unroll
        for (int h = 0; h < NH; h++)
            #pragma unroll
            for (int i = 0; i < TI; i++) acc[h][i] = 0.f;

        #pragma unroll
        for (int h = 0; h < NH; h++) {
            #pragma unroll
            for (int d = 0; d < DD; d++) {
                const int hd = h*DD + d;
                const float kt = KtB[hd*NN + j];           // coalesced LDG
                const float4 qa = *(const float4*)&s_qt[hd*TI];     // broadcast
                const float4 qb = *(const float4*)&s_qt[hd*TI + 4];
                acc[h][0] = fmaf(qa.x, kt, acc[h][0]);
                acc[h][1] = fmaf(qa.y, kt, acc[h][1]);
                acc[h][2] = fmaf(qa.z, kt, acc[h][2]);
                acc[h][3] = fmaf(qa.w, kt, acc[h][3]);
                acc[h][4] = fmaf(qb.x, kt, acc[h][4]);
                acc[h][5] = fmaf(qb.y, kt, acc[h][5]);
                acc[h][6] = fmaf(qb.z, kt, acc[h][6]);
                acc[h][7] = fmaf(qb.w, kt, acc[h][7]);
            }
        }
        #pragma unroll
        for (int i = 0; i < TI; i++) {
            const bool on = (am >> i) & 1u;
            #pragma unroll
            for (int h = 0; h < NH; h++) {
                const float e = on
                    ? __expf((acc[h][i] + ev[i]*s_qw[i*NH + h]
                              + s_qb[i*NH + h]) * SCALE)
                    : 0.f;
                s_sc[(i*NH + h)*NN + j] = e;
            }
        }
    }
    __syncthreads();

    // ---- Phase 2: per-unit sum -> 1/sum. warp w does units w, w+16. ----
    {
        const int w = tid >> 5, lane = tid & 31;
        #pragma unroll
        for (int uu = 0; uu < 2; uu++) {
            const int u = w + 16*uu;
            const float* row = &s_sc[u*NN];
            float sum = 0.f;
            #pragma unroll
            for (int k = 0; k < 16; k++) sum += row[lane + 32*k];
            #pragma unroll
            for (int o = 16; o; o >>= 1) sum += __shfl_xor_sync(0xffffffffu, sum, o);
            if (lane == 0) s_inv[u] = 1.f / sum;
        }
    }
    __syncthreads();

    // ---- Phase 3: msg = (E @ V) * inv. thread = (slice of j, col c). ----
    {
        const int slice = tid >> 6;   // 0..7
        const int c     = tid & 63;   // h*16+d
        const int h     = c >> 4;
        float acc[TI];
        #pragma unroll
        for (int i = 0; i < TI; i++) acc[i] = 0.f;
        const float* Vb = &g_V[(long)b*NN*HH];
        #pragma unroll
        for (int js = 0; js < 16; js++) {
            const int jx = slice*64 + js*4;
            const float v0 = Vb[(jx+0)*HH + c];
            const float v1 = Vb[(jx+1)*HH + c];
            const float v2 = Vb[(jx+2)*HH + c];
            const float v3 = Vb[(jx+3)*HH + c];
            #pragma unroll
            for (int i = 0; i < TI; i++) {
                const float4 p = *(const float4*)&s_sc[(i*NH + h)*NN + jx];
                acc[i] = fmaf(p.x, v0, acc[i]);
                acc[i] = fmaf(p.y, v1, acc[i]);
                acc[i] = fmaf(p.z, v2, acc[i]);
                acc[i] = fmaf(p.w, v3, acc[i]);
            }
        }
        #pragma unroll
        for (int i = 0; i < TI; i++)
            s_red[(slice*TI + i)*HH + c] = acc[i] * s_inv[i*NH + h];
    }
    __syncthreads();

    // ---- Phase 3b: reduce slices + residual. tid covers TI*HH = 512. ----
    {
        const int i = tid >> 6, c = tid & 63;
        float m = 0.f;
        #pragma unroll
        for (int s = 0; s < 8; s++) m += s_red[(s*TI + i)*HH + c];
        const long r = (long)(b*NN + i0 + i)*HH + c;
        s_y[i*HH + c] = x[r] + g_T[r] + m;
    }
    __syncthreads();

    // ---- Phase 4: LayerNorm. warp w handles row i=w (TI*32 = 256 threads). -
    if (tid < TI*32) {
        const int i = tid >> 5, l = tid & 31;
        const float y0 = s_y[i*HH + l];
        const float y1 = s_y[i*HH + l + 32];
        float s  = y0 + y1;
        float sq = y0*y0 + y1*y1;
        #pragma unroll
        for (int o = 16; o; o >>= 1) {
            s  += __shfl_xor_sync(0xffffffffu, s,  o);
            sq += __shfl_xor_sync(0xffffffffu, sq, o);
        }
        const float mean = s * (1.f/64.f);
        const float var  = sq * (1.f/64.f) - mean*mean;
        const float rs   = rsqrtf(var + LN_EPS);
        float* op = &out[(long)(b*NN + i0 + i)*HH];
        op[l]      = (y0 - mean)*rs*lng[l]      + lnb[l];
        op[l + 32] = (y1 - mean)*rs*lng[l + 32] + lnb[l + 32];
    }
}

// ---------------------------------------------------------------------------
extern "C" void kernel_launch(void* const* d_in, const int* in_sizes, int n_in,
                              void* d_out, int out_size)
{
    const float* x   = (const float*)d_in[0];
    const int*   adj = (const int*)  d_in[1];
    const float* ef  = (const float*)d_in[2];
    const float* W1w = (const float*)d_in[3];
    const float* W1b = (const float*)d_in[4];
    const float* W2w = (const float*)d_in[5];
    const float* W2b = (const float*)d_in[6];
    const float* W3w = (const float*)d_in[7];
    const float* W3b = (const float*)d_in[8];
    const float* W4w = (const float*)d_in[9];
    const float* W4b = (const float*)d_in[10];
    const float* W5w = (const float*)d_in[11];
    const float* W5b = (const float*)d_in[12];
    const float* lng = (const float*)d_in[13];
    const float* lnb = (const float*)d_in[14];

    cudaFuncSetAttribute(attn_kernel,
                         cudaFuncAttributeMaxDynamicSharedMemorySize, SM_BYTES);

    proj_kernel<<<BB*NN/4, 64>>>(x, W1w, W1b, W2w, W2b, W3w, W3b,
                                 W4w, W4b, W5w, W5b);
    attn_kernel<<<BB*NN/TI, 512, SM_BYTES>>>(x, adj, ef, lng, lnb,
                                             (float*)d_out);
}

// round 13
// speedup vs baseline: 1.2230x; 1.0669x over previous
#include <cuda_runtime.h>
#include <math.h>

#define BB 4
#define NN 512
#define HH 64
#define NH 4
#define DD 16
#define SCALE 0.25f      // 1/sqrt(16)
#define LN_EPS 1e-5f
#define TI 8             // query rows per attn block

// Scratch (allocation-free: __device__ globals)
__device__ float g_T [BB*NN*HH];
__device__ float g_Q [BB*NN*HH];   // pre-scaled by SCALE
__device__ float g_Kt[BB*HH*NN];   // K transposed: [b][hd][j]
__device__ float g_V [BB*NN*HH];
__device__ float g_qw5[BB*NN*NH];  // pre-scaled (derived from scaled Q)
__device__ float g_qb5[BB*NN*NH];  // pre-scaled

// ---------------------------------------------------------------------------
// Kernel 1: node projections. 512 blocks x 256 threads. Block does 4 rows;
// thread group g (64 threads, warp-uniform) computes ONLY matrix Wg for all
// 4 rows: 256 FMA/thread, 64 weight LDGs. ~3.5 blocks/SM, 28 warps/SM.
// Q is written pre-scaled by SCALE (folded out of the attn epilogue).
// ---------------------------------------------------------------------------
__global__ __launch_bounds__(256)
void proj_kernel(const float* __restrict__ x,
    const float* __restrict__ W1w, const float* __restrict__ W1b,
    const float* __restrict__ W2w, const float* __restrict__ W2b,
    const float* __restrict__ W3w, const float* __restrict__ W3b,
    const float* __restrict__ W4w, const float* __restrict__ W4b,
    const float* __restrict__ W5w, const float* __restrict__ W5b)
{
    const int g = threadIdx.x >> 6;        // 0:T 1:V 2:Q 3:K
    const int t = threadIdx.x & 63;        // out column
    const int row0 = blockIdx.x * 4;

    __shared__ float sx[4][64];
    __shared__ float sq[4][64];

    // stage the 4 input rows (256 threads = 4 rows x 64 cols)
    sx[g][t] = x[(row0 + g)*HH + t];
    __syncthreads();

    const float* Ww = (g == 0) ? W1w : (g == 1) ? W2w : (g == 2) ? W3w : W4w;
    const float* Wb = (g == 0) ? W1b : (g == 1) ? W2b : (g == 2) ? W3b : W4b;

    float a[4] = {0.f, 0.f, 0.f, 0.f};
    #pragma unroll 16
    for (int k = 0; k < 64; k++) {
        const float w = Ww[k*64 + t];
        #pragma unroll
        for (int r = 0; r < 4; r++) a[r] = fmaf(sx[r][k], w, a[r]);
    }
    const float bb = Wb[t];

    if (g == 0) {
        #pragma unroll
        for (int r = 0; r < 4; r++) g_T[(row0 + r)*HH + t] = a[r] + bb;
    } else if (g == 1) {
        #pragma unroll
        for (int r = 0; r < 4; r++) g_V[(row0 + r)*HH + t] = a[r] + bb;
    } else if (g == 2) {
        #pragma unroll
        for (int r = 0; r < 4; r++) {
            const float q = (a[r] + bb) * SCALE;   // fold SCALE into Q
            g_Q[(row0 + r)*HH + t] = q;
            sq[r][t] = q;
        }
    } else {
        // K transposed: thread owns column t, nodes n0..n0+3 contiguous in Kt
        const int bq = row0 >> 9;          // / NN
        const int n0 = row0 & (NN - 1);
        float* kt = &g_Kt[((long)bq*HH + t)*NN + n0];
        *(float4*)(kt) = make_float4(a[0]+bb, a[1]+bb, a[2]+bb, a[3]+bb);
    }
    __syncthreads();

    // qw5/qb5 (scaled, since sq is scaled): 16 (r,h) pairs
    if (threadIdx.x < 16) {
        const int r = threadIdx.x >> 2, h = threadIdx.x & 3;
        float sw = 0.f, sb = 0.f;
        #pragma unroll
        for (int d = 0; d < 16; d++) {
            const float q = sq[r][h*16 + d];
            sw = fmaf(q, W5w[h*16 + d], sw);
            sb = fmaf(q, W5b[h*16 + d], sb);
        }
        g_qw5[(row0 + r)*NH + h] = sw;
        g_qb5[(row0 + r)*NH + h] = sb;
    }
}

// ---------------------------------------------------------------------------
// Kernel 2: fused scores+exp + sum + attn*V(normalized) + residual + LN.
// One block per (b, TI=8 query rows). 512 threads. Dynamic smem (~86 KB).
// launch_bounds(512,2) pins regs at 64 -> 2 blocks/SM.
// Q (and qw5/qb5) arrive pre-scaled, so the epilogue needs no *SCALE.
// ---------------------------------------------------------------------------
#define SM_FLOATS (TI*NH*NN + HH*TI + TI*NH + TI*NH + 32 + 8*TI*HH + TI*HH)
#define SM_BYTES  (SM_FLOATS * 4)

__global__ __launch_bounds__(512, 2)
void attn_kernel(const float* __restrict__ x,
                 const int*   __restrict__ adj,
                 const float* __restrict__ ef,
                 const float* __restrict__ lng,
                 const float* __restrict__ lnb,
                 float* __restrict__ out)
{
    extern __shared__ float smem[];
    float* s_sc  = smem;                   // [TI*NH][NN] exp(scores)
    float* s_qt  = s_sc + TI*NH*NN;        // [HH][TI]  Q transposed
    float* s_qw  = s_qt + HH*TI;           // TI*NH
    float* s_qb  = s_qw + TI*NH;           // TI*NH
    float* s_inv = s_qb + TI*NH;           // 32: 1/sum per unit
    float* s_red = s_inv + 32;             // [8][TI*HH]
    float* s_y   = s_red + 8*TI*HH;        // TI*HH

    const int tid = threadIdx.x;                  // 0..511
    const int b   = blockIdx.x / (NN / TI);
    const int i0  = (blockIdx.x % (NN / TI)) * TI;

    // Stage Q transposed: s_qt[hd][i]
    {
        const int i = tid >> 6, hd = tid & 63;
        s_qt[hd*TI + i] = g_Q[(b*NN + i0 + i)*HH + hd];
    }
    if (tid < TI*NH) {
        s_qw[tid] = g_qw5[(b*NN + i0)*NH + tid];
        s_qb[tid] = g_qb5[(b*NN + i0)*NH + tid];
    }
    __syncthreads();

    // ---- Phase 1: scores + exp. thread j streams Kt coalesced. ----
    {
        const int j = tid;
        const float* KtB = &g_Kt[(long)b*HH*NN];
        float ev[TI];
        unsigned int am = 0;     // adjacency bitmask (bit i)
        #pragma unroll
        for (int i = 0; i < TI; i++) {
            const long base = (long)(b*NN + i0 + i)*NN + j;
            ev[i] = ef[base];
            am |= (adj[base] ? 1u : 0u) << i;
        }
        float acc[NH][TI];
        #pragma unroll
        for (int h = 0; h < NH; h++)
            #pragma unroll
            for (int i = 0; i < TI; i++) acc[h][i] = 0.f;

        #pragma unroll
        for (int h = 0; h < NH; h++) {
            #pragma unroll
            for (int d = 0; d < DD; d++) {
                const int hd = h*DD + d;
                const float kt = KtB[hd*NN + j];           // coalesced LDG
                const float4 qa = *(const float4*)&s_qt[hd*TI];     // broadcast
                const float4 qb = *(const float4*)&s_qt[hd*TI + 4];
                acc[h][0] = fmaf(qa.x, kt, acc[h][0]);
                acc[h][1] = fmaf(qa.y, kt, acc[h][1]);
                acc[h][2] = fmaf(qa.z, kt, acc[h][2]);
                acc[h][3] = fmaf(qa.w, kt, acc[h][3]);
                acc[h][4] = fmaf(qb.x, kt, acc[h][4]);
                acc[h][5] = fmaf(qb.y, kt, acc[h][5]);
                acc[h][6] = fmaf(qb.z, kt, acc[h][6]);
                acc[h][7] = fmaf(qb.w, kt, acc[h][7]);
            }
        }
        #pragma unroll
        for (int i = 0; i < TI; i++) {
            const bool on = (am >> i) & 1u;
            #pragma unroll
            for (int h = 0; h < NH; h++) {
                const float e = on
                    ? __expf(acc[h][i] + ev[i]*s_qw[i*NH + h] + s_qb[i*NH + h])
                    : 0.f;
                s_sc[(i*NH + h)*NN + j] = e;
            }
        }
    }
    __syncthreads();

    // ---- Phase 2: per-unit sum -> 1/sum. warp w does units w, w+16. ----
    {
        const int w = tid >> 5, lane = tid & 31;
        #pragma unroll
        for (int uu = 0; uu < 2; uu++) {
            const int u = w + 16*uu;
            const float* row = &s_sc[u*NN];
            float sum = 0.f;
            #pragma unroll
            for (int k = 0; k < 16; k++) sum += row[lane + 32*k];
            #pragma unroll
            for (int o = 16; o; o >>= 1) sum += __shfl_xor_sync(0xffffffffu, sum, o);
            if (lane == 0) s_inv[u] = 1.f / sum;
        }
    }
    __syncthreads();

    // ---- Phase 3: msg = (E @ V) * inv. thread = (slice of j, col c). ----
    {
        const int slice = tid >> 6;   // 0..7
        const int c     = tid & 63;   // h*16+d
        const int h     = c >> 4;
        float acc[TI];
        #pragma unroll
        for (int i = 0; i < TI; i++) acc[i] = 0.f;
        const float* Vb = &g_V[(long)b*NN*HH];
        #pragma unroll
        for (int js = 0; js < 16; js++) {
            const int jx = slice*64 + js*4;
            const float v0 = Vb[(jx+0)*HH + c];
            const float v1 = Vb[(jx+1)*HH + c];
            const float v2 = Vb[(jx+2)*HH + c];
            const float v3 = Vb[(jx+3)*HH + c];
            #pragma unroll
            for (int i = 0; i < TI; i++) {
                const float4 p = *(const float4*)&s_sc[(i*NH + h)*NN + jx];
                acc[i] = fmaf(p.x, v0, acc[i]);
                acc[i] = fmaf(p.y, v1, acc[i]);
                acc[i] = fmaf(p.z, v2, acc[i]);
                acc[i] = fmaf(p.w, v3, acc[i]);
            }
        }
        #pragma unroll
        for (int i = 0; i < TI; i++)
            s_red[(slice*TI + i)*HH + c] = acc[i] * s_inv[i*NH + h];
    }
    __syncthreads();

    // ---- Phase 3b: reduce slices + residual. tid covers TI*HH = 512. ----
    {
        const int i = tid >> 6, c = tid & 63;
        float m = 0.f;
        #pragma unroll
        for (int s = 0; s < 8; s++) m += s_red[(s*TI + i)*HH + c];
        const long r = (long)(b*NN + i0 + i)*HH + c;
        s_y[i*HH + c] = x[r] + g_T[r] + m;
    }
    __syncthreads();

    // ---- Phase 4: LayerNorm. warp w handles row i=w (TI*32 = 256 threads). -
    if (tid < TI*32) {
        const int i = tid >> 5, l = tid & 31;
        const float y0 = s_y[i*HH + l];
        const float y1 = s_y[i*HH + l + 32];
        float s  = y0 + y1;
        float sq = y0*y0 + y1*y1;
        #pragma unroll
        for (int o = 16; o; o >>= 1) {
            s  += __shfl_xor_sync(0xffffffffu, s,  o);
            sq += __shfl_xor_sync(0xffffffffu, sq, o);
        }
        const float mean = s * (1.f/64.f);
        const float var  = sq * (1.f/64.f) - mean*mean;
        const float rs   = rsqrtf(var + LN_EPS);
        float* op = &out[(long)(b*NN + i0 + i)*HH];
        op[l]      = (y0 - mean)*rs*lng[l]      + lnb[l];
        op[l + 32] = (y1 - mean)*rs*lng[l + 32] + lnb[l + 32];
    }
}

// ---------------------------------------------------------------------------
extern "C" void kernel_launch(void* const* d_in, const int* in_sizes, int n_in,
                              void* d_out, int out_size)
{
    const float* x   = (const float*)d_in[0];
    const int*   adj = (const int*)  d_in[1];
    const float* ef  = (const float*)d_in[2];
    const float* W1w = (const float*)d_in[3];
    const float* W1b = (const float*)d_in[4];
    const float* W2w = (const float*)d_in[5];
    const float* W2b = (const float*)d_in[6];
    const float* W3w = (const float*)d_in[7];
    const float* W3b = (const float*)d_in[8];
    const float* W4w = (const float*)d_in[9];
    const float* W4b = (const float*)d_in[10];
    const float* W5w = (const float*)d_in[11];
    const float* W5b = (const float*)d_in[12];
    const float* lng = (const float*)d_in[13];
    const float* lnb = (const float*)d_in[14];

    cudaFuncSetAttribute(attn_kernel,
                         cudaFuncAttributeMaxDynamicSharedMemorySize, SM_BYTES);

    proj_kernel<<<BB*NN/4, 256>>>(x, W1w, W1b, W2w, W2b, W3w, W3b,
                                  W4w, W4b, W5w, W5b);
    attn_kernel<<<BB*NN/TI, 512, SM_BYTES>>>(x, adj, ef, lng, lnb,
                                             (float*)d_out);
}

// round 14
// speedup vs baseline: 1.3313x; 1.0886x over previous
#include <cuda_runtime.h>
#include <math.h>

#define BB 4
#define NN 512
#define SCP (NN + 4)     // padded score-row stride (bank-conflict-free over h)
#define HH 64
#define NH 4
#define DD 16
#define SCALE 0.25f      // 1/sqrt(16)
#define LN_EPS 1e-5f
#define TI 8             // query rows per attn block
#define NSL 16           // j-slices in phase 3

// Scratch (allocation-free: __device__ globals)
__device__ float g_T [BB*NN*HH];
__device__ float g_Q [BB*NN*HH];   // pre-scaled by SCALE
__device__ float g_Kt[BB*HH*NN];   // K transposed: [b][hd][j]
__device__ float g_V [BB*NN*HH];
__device__ float g_qw5[BB*NN*NH];  // pre-scaled (derived from scaled Q)
__device__ float g_qb5[BB*NN*NH];  // pre-scaled

// ---------------------------------------------------------------------------
// Kernel 1: node projections. 512 blocks x 256 threads. Block does 4 rows;
// thread group g (64 threads, warp-uniform) computes ONLY matrix Wg for all
// 4 rows. Q written pre-scaled by SCALE.
// ---------------------------------------------------------------------------
__global__ __launch_bounds__(256)
void proj_kernel(const float* __restrict__ x,
    const float* __restrict__ W1w, const float* __restrict__ W1b,
    const float* __restrict__ W2w, const float* __restrict__ W2b,
    const float* __restrict__ W3w, const float* __restrict__ W3b,
    const float* __restrict__ W4w, const float* __restrict__ W4b,
    const float* __restrict__ W5w, const float* __restrict__ W5b)
{
    const int g = threadIdx.x >> 6;        // 0:T 1:V 2:Q 3:K
    const int t = threadIdx.x & 63;        // out column
    const int row0 = blockIdx.x * 4;

    __shared__ float sx[4][64];
    __shared__ float sq[4][64];

    sx[g][t] = x[(row0 + g)*HH + t];
    __syncthreads();

    const float* Ww = (g == 0) ? W1w : (g == 1) ? W2w : (g == 2) ? W3w : W4w;
    const float* Wb = (g == 0) ? W1b : (g == 1) ? W2b : (g == 2) ? W3b : W4b;

    float a[4] = {0.f, 0.f, 0.f, 0.f};
    #pragma unroll 16
    for (int k = 0; k < 64; k++) {
        const float w = Ww[k*64 + t];
        #pragma unroll
        for (int r = 0; r < 4; r++) a[r] = fmaf(sx[r][k], w, a[r]);
    }
    const float bb = Wb[t];

    if (g == 0) {
        #pragma unroll
        for (int r = 0; r < 4; r++) g_T[(row0 + r)*HH + t] = a[r] + bb;
    } else if (g == 1) {
        #pragma unroll
        for (int r = 0; r < 4; r++) g_V[(row0 + r)*HH + t] = a[r] + bb;
    } else if (g == 2) {
        #pragma unroll
        for (int r = 0; r < 4; r++) {
            const float q = (a[r] + bb) * SCALE;   // fold SCALE into Q
            g_Q[(row0 + r)*HH + t] = q;
            sq[r][t] = q;
        }
    } else {
        const int bq = row0 >> 9;          // / NN
        const int n0 = row0 & (NN - 1);
        float* kt = &g_Kt[((long)bq*HH + t)*NN + n0];
        *(float4*)(kt) = make_float4(a[0]+bb, a[1]+bb, a[2]+bb, a[3]+bb);
    }
    __syncthreads();

    if (threadIdx.x < 16) {
        const int r = threadIdx.x >> 2, h = threadIdx.x & 3;
        float sw = 0.f, sb = 0.f;
        #pragma unroll
        for (int d = 0; d < 16; d++) {
            const float q = sq[r][h*16 + d];
            sw = fmaf(q, W5w[h*16 + d], sw);
            sb = fmaf(q, W5b[h*16 + d], sb);
        }
        g_qw5[(row0 + r)*NH + h] = sw;
        g_qb5[(row0 + r)*NH + h] = sb;
    }
}

// ---------------------------------------------------------------------------
// Kernel 2: fused scores+exp + sum + attn*V(normalized) + residual + LN.
// One block per (b, TI=8 query rows). 512 threads. ~103 KB dynamic smem,
// launch_bounds(512,2) pins regs at 64 -> 2 blocks/SM.
// s_sc rows padded to SCP=NN+4 so different h-rows hit distinct banks.
// ---------------------------------------------------------------------------
#define SM_FLOATS (TI*NH*SCP + HH*TI + TI*NH + TI*NH + 32 + NSL*TI*HH + TI*HH)
#define SM_BYTES  (SM_FLOATS * 4)

__global__ __launch_bounds__(512, 2)
void attn_kernel(const float* __restrict__ x,
                 const int*   __restrict__ adj,
                 const float* __restrict__ ef,
                 const float* __restrict__ lng,
                 const float* __restrict__ lnb,
                 float* __restrict__ out)
{
    extern __shared__ float smem[];
    float* s_sc  = smem;                   // [TI*NH][SCP] exp(scores)
    float* s_qt  = s_sc + TI*NH*SCP;       // [HH][TI]  Q transposed
    float* s_qw  = s_qt + HH*TI;           // TI*NH
    float* s_qb  = s_qw + TI*NH;           // TI*NH
    float* s_inv = s_qb + TI*NH;           // 32: 1/sum per unit
    float* s_red = s_inv + 32;             // [NSL][TI*HH]
    float* s_y   = s_red + NSL*TI*HH;      // TI*HH

    const int tid = threadIdx.x;                  // 0..511
    const int b   = blockIdx.x / (NN / TI);
    const int i0  = (blockIdx.x % (NN / TI)) * TI;

    // Stage Q transposed: s_qt[hd][i]
    {
        const int i = tid >> 6, hd = tid & 63;
        s_qt[hd*TI + i] = g_Q[(b*NN + i0 + i)*HH + hd];
    }
    if (tid < TI*NH) {
        s_qw[tid] = g_qw5[(b*NN + i0)*NH + tid];
        s_qb[tid] = g_qb5[(b*NN + i0)*NH + tid];
    }
    __syncthreads();

    // ---- Phase 1: scores + exp. thread = (head-pair hp, j-pair jp). ----
    {
        const int hp = tid >> 8;            // 0/1: heads {0,1} or {2,3}
        const int jp = tid & 255;
        const int j0 = jp * 2;
        const float* KtB = &g_Kt[(long)b*HH*NN];

        // acc[hh][jj][i], initialized with the edge term ev*qw5 + qb5
        float acc[2][2][TI];
        unsigned int am = 0;                // mask bit (2*i + jj)
        #pragma unroll
        for (int i = 0; i < TI; i++) {
            const long base = (long)(b*NN + i0 + i)*NN + j0;
            const float2 e2 = *(const float2*)&ef[base];
            const int2  a2 = *(const int2*)&adj[base];
            am |= (a2.x ? 1u : 0u) << (2*i);
            am |= (a2.y ? 1u : 0u) << (2*i + 1);
            const float2 qw = *(const float2*)&s_qw[i*NH + hp*2];
            const float2 qb = *(const float2*)&s_qb[i*NH + hp*2];
            acc[0][0][i] = fmaf(e2.x, qw.x, qb.x);
            acc[0][1][i] = fmaf(e2.y, qw.x, qb.x);
            acc[1][0][i] = fmaf(e2.x, qw.y, qb.y);
            acc[1][1][i] = fmaf(e2.y, qw.y, qb.y);
        }

        #pragma unroll
        for (int hh = 0; hh < 2; hh++) {
            const int h = hp*2 + hh;
            #pragma unroll
            for (int d = 0; d < DD; d++) {
                const int hd = h*DD + d;
                const float2 kt = *(const float2*)&KtB[hd*NN + j0];  // LDG.64
                const float4 qa = *(const float4*)&s_qt[hd*TI];      // bcast
                const float4 qc = *(const float4*)&s_qt[hd*TI + 4];
                acc[hh][0][0] = fmaf(qa.x, kt.x, acc[hh][0][0]);
                acc[hh][1][0] = fmaf(qa.x, kt.y, acc[hh][1][0]);
                acc[hh][0][1] = fmaf(qa.y, kt.x, acc[hh][0][1]);
                acc[hh][1][1] = fmaf(qa.y, kt.y, acc[hh][1][1]);
                acc[hh][0][2] = fmaf(qa.z, kt.x, acc[hh][0][2]);
                acc[hh][1][2] = fmaf(qa.z, kt.y, acc[hh][1][2]);
                acc[hh][0][3] = fmaf(qa.w, kt.x, acc[hh][0][3]);
                acc[hh][1][3] = fmaf(qa.w, kt.y, acc[hh][1][3]);
                acc[hh][0][4] = fmaf(qc.x, kt.x, acc[hh][0][4]);
                acc[hh][1][4] = fmaf(qc.x, kt.y, acc[hh][1][4]);
                acc[hh][0][5] = fmaf(qc.y, kt.x, acc[hh][0][5]);
                acc[hh][1][5] = fmaf(qc.y, kt.y, acc[hh][1][5]);
                acc[hh][0][6] = fmaf(qc.z, kt.x, acc[hh][0][6]);
                acc[hh][1][6] = fmaf(qc.z, kt.y, acc[hh][1][6]);
                acc[hh][0][7] = fmaf(qc.w, kt.x, acc[hh][0][7]);
                acc[hh][1][7] = fmaf(qc.w, kt.y, acc[hh][1][7]);
            }
        }

        #pragma unroll
        for (int i = 0; i < TI; i++) {
            const bool on0 = (am >> (2*i))     & 1u;
            const bool on1 = (am >> (2*i + 1)) & 1u;
            #pragma unroll
            for (int hh = 0; hh < 2; hh++) {
                const int h = hp*2 + hh;
                float2 e;
                e.x = on0 ? __expf(acc[hh][0][i]) : 0.f;
                e.y = on1 ? __expf(acc[hh][1][i]) : 0.f;
                *(float2*)&s_sc[(i*NH + h)*SCP + j0] = e;
            }
        }
    }
    __syncthreads();

    // ---- Phase 2: per-unit sum -> 1/sum. warp w does units w, w+16. ----
    {
        const int w = tid >> 5, lane = tid & 31;
        #pragma unroll
        for (int uu = 0; uu < 2; uu++) {
            const int u = w + 16*uu;
            const float* row = &s_sc[u*SCP];
            float sum = 0.f;
            #pragma unroll
            for (int k = 0; k < 16; k++) sum += row[lane + 32*k];
            #pragma unroll
            for (int o = 16; o; o >>= 1) sum += __shfl_xor_sync(0xffffffffu, sum, o);
            if (lane == 0) s_inv[u] = 1.f / sum;
        }
    }
    __syncthreads();

    // ---- Phase 3: msg = (E @ V) * inv. thread = (32-j slice, c-pair). ----
    {
        const int slice = tid >> 5;   // 0..15, 32 j each
        const int cp    = tid & 31;
        const int c0    = cp * 2;     // output cols c0, c0+1
        const int h     = cp >> 3;    // head of both cols
        float acc0[TI], acc1[TI];
        #pragma unroll
        for (int i = 0; i < TI; i++) { acc0[i] = 0.f; acc1[i] = 0.f; }
        const float* Vb = &g_V[(long)b*NN*HH];
        #pragma unroll
        for (int js = 0; js < 8; js++) {
            const int jx = slice*32 + js*4;
            const float2 v0 = *(const float2*)&Vb[(jx+0)*HH + c0];
            const float2 v1 = *(const float2*)&Vb[(jx+1)*HH + c0];
            const float2 v2 = *(const float2*)&Vb[(jx+2)*HH + c0];
            const float2 v3 = *(const float2*)&Vb[(jx+3)*HH + c0];
            #pragma unroll
            for (int i = 0; i < TI; i++) {
                const float4 p = *(const float4*)&s_sc[(i*NH + h)*SCP + jx];
                acc0[i] = fmaf(p.x, v0.x, acc0[i]);
                acc1[i] = fmaf(p.x, v0.y, acc1[i]);
                acc0[i] = fmaf(p.y, v1.x, acc0[i]);
                acc1[i] = fmaf(p.y, v1.y, acc1[i]);
                acc0[i] = fmaf(p.z, v2.x, acc0[i]);
                acc1[i] = fmaf(p.z, v2.y, acc1[i]);
                acc0[i] = fmaf(p.w, v3.x, acc0[i]);
                acc1[i] = fmaf(p.w, v3.y, acc1[i]);
            }
        }
        #pragma unroll
        for (int i = 0; i < TI; i++) {
            const float inv = s_inv[i*NH + h];
            float2 r; r.x = acc0[i]*inv; r.y = acc1[i]*inv;
            *(float2*)&s_red[(slice*TI + i)*HH + c0] = r;
        }
    }
    __syncthreads();

    // ---- Phase 3b: reduce slices + residual. tid covers TI*HH = 512. ----
    {
        const int i = tid >> 6, c = tid & 63;
        float m = 0.f;
        #pragma unroll
        for (int s = 0; s < NSL; s++) m += s_red[(s*TI + i)*HH + c];
        const long r = (long)(b*NN + i0 + i)*HH + c;
        s_y[i*HH + c] = x[r] + g_T[r] + m;
    }
    __syncthreads();

    // ---- Phase 4: LayerNorm. warp w handles row i=w (TI*32 = 256 threads). -
    if (tid < TI*32) {
        const int i = tid >> 5, l = tid & 31;
        const float y0 = s_y[i*HH + l];
        const float y1 = s_y[i*HH + l + 32];
        float s  = y0 + y1;
        float sq = y0*y0 + y1*y1;
        #pragma unroll
        for (int o = 16; o; o >>= 1) {
            s  += __shfl_xor_sync(0xffffffffu, s,  o);
            sq += __shfl_xor_sync(0xffffffffu, sq, o);
        }
        const float mean = s * (1.f/64.f);
        const float var  = sq * (1.f/64.f) - mean*mean;
        const float rs   = rsqrtf(var + LN_EPS);
        float* op = &out[(long)(b*NN + i0 + i)*HH];
        op[l]      = (y0 - mean)*rs*lng[l]      + lnb[l];
        op[l + 32] = (y1 - mean)*rs*lng[l + 32] + lnb[l + 32];
    }
}

// ---------------------------------------------------------------------------
extern "C" void kernel_launch(void* const* d_in, const int* in_sizes, int n_in,
                              void* d_out, int out_size)
{
    const float* x   = (const float*)d_in[0];
    const int*   adj = (const int*)  d_in[1];
    const float* ef  = (const float*)d_in[2];
    const float* W1w = (const float*)d_in[3];
    const float* W1b = (const float*)d_in[4];
    const float* W2w = (const float*)d_in[5];
    const float* W2b = (const float*)d_in[6];
    const float* W3w = (const float*)d_in[7];
    const float* W3b = (const float*)d_in[8];
    const float* W4w = (const float*)d_in[9];
    const float* W4b = (const float*)d_in[10];
    const float* W5w = (const float*)d_in[11];
    const float* W5b = (const float*)d_in[12];
    const float* lng = (const float*)d_in[13];
    const float* lnb = (const float*)d_in[14];

    cudaFuncSetAttribute(attn_kernel,
                         cudaFuncAttributeMaxDynamicSharedMemorySize, SM_BYTES);

    proj_kernel<<<BB*NN/4, 256>>>(x, W1w, W1b, W2w, W2b, W3w, W3b,
                                  W4w, W4b, W5w, W5b);
    attn_kernel<<<BB*NN/TI, 512, SM_BYTES>>>(x, adj, ef, lng, lnb,
                                             (float*)d_out);
}

// round 15
// speedup vs baseline: 1.4302x; 1.0743x over previous
#include <cuda_runtime.h>
#include <math.h>

#define BB 4
#define NN 512
#define SCP (NN + 4)     // padded score-row stride (bank-conflict-free over h)
#define HH 64
#define NH 4
#define DD 16
#define SCALE 0.25f      // 1/sqrt(16)
#define LN_EPS 1e-5f
#define TI 8             // query rows per attn block
#define NSL 16           // j-slices in phase 3

// Scratch (allocation-free: __device__ globals)
__device__ float g_T [BB*NN*HH];
__device__ float g_Q [BB*NN*HH];   // pre-scaled by SCALE
__device__ float g_Kt[BB*HH*NN];   // K transposed: [b][hd][j]
__device__ float g_V [BB*NN*HH];
__device__ float g_qw5[BB*NN*NH];  // pre-scaled (derived from scaled Q)
__device__ float g_qb5[BB*NN*NH];  // pre-scaled

// ---------------------------------------------------------------------------
// Kernel 1: node projections. 256 blocks x 256 threads, 8 rows/block.
// Thread group g (64 threads, warp-uniform) computes ONLY matrix Wg for all
// 8 rows (512 FMA/thread). Halves L2 weight-broadcast traffic vs 512 blocks.
// Q written pre-scaled by SCALE.
// ---------------------------------------------------------------------------
__global__ __launch_bounds__(256)
void proj_kernel(const float* __restrict__ x,
    const float* __restrict__ W1w, const float* __restrict__ W1b,
    const float* __restrict__ W2w, const float* __restrict__ W2b,
    const float* __restrict__ W3w, const float* __restrict__ W3b,
    const float* __restrict__ W4w, const float* __restrict__ W4b,
    const float* __restrict__ W5w, const float* __restrict__ W5b)
{
    const int g = threadIdx.x >> 6;        // 0:T 1:V 2:Q 3:K
    const int t = threadIdx.x & 63;        // out column
    const int row0 = blockIdx.x * 8;

    __shared__ float sx[8][64];
    __shared__ float sq[8][64];

    // stage the 8 input rows (256 threads: group g loads rows g and g+4)
    sx[g][t]     = x[(row0 + g)*HH + t];
    sx[g + 4][t] = x[(row0 + g + 4)*HH + t];
    __syncthreads();

    const float* Ww = (g == 0) ? W1w : (g == 1) ? W2w : (g == 2) ? W3w : W4w;
    const float* Wb = (g == 0) ? W1b : (g == 1) ? W2b : (g == 2) ? W3b : W4b;

    float a[8];
    #pragma unroll
    for (int r = 0; r < 8; r++) a[r] = 0.f;
    #pragma unroll 8
    for (int k = 0; k < 64; k++) {
        const float w = Ww[k*64 + t];
        #pragma unroll
        for (int r = 0; r < 8; r++) a[r] = fmaf(sx[r][k], w, a[r]);
    }
    const float bb = Wb[t];

    if (g == 0) {
        #pragma unroll
        for (int r = 0; r < 8; r++) g_T[(row0 + r)*HH + t] = a[r] + bb;
    } else if (g == 1) {
        #pragma unroll
        for (int r = 0; r < 8; r++) g_V[(row0 + r)*HH + t] = a[r] + bb;
    } else if (g == 2) {
        #pragma unroll
        for (int r = 0; r < 8; r++) {
            const float q = (a[r] + bb) * SCALE;   // fold SCALE into Q
            g_Q[(row0 + r)*HH + t] = q;
            sq[r][t] = q;
        }
    } else {
        // K transposed: thread owns column t, nodes n0..n0+7 contiguous in Kt
        const int bq = row0 >> 9;          // / NN
        const int n0 = row0 & (NN - 1);
        float* kt = &g_Kt[((long)bq*HH + t)*NN + n0];
        *(float4*)(kt)     = make_float4(a[0]+bb, a[1]+bb, a[2]+bb, a[3]+bb);
        *(float4*)(kt + 4) = make_float4(a[4]+bb, a[5]+bb, a[6]+bb, a[7]+bb);
    }
    __syncthreads();

    // qw5/qb5 (scaled): 32 (r,h) pairs
    if (threadIdx.x < 32) {
        const int r = threadIdx.x >> 2, h = threadIdx.x & 3;
        float sw = 0.f, sb = 0.f;
        #pragma unroll
        for (int d = 0; d < 16; d++) {
            const float q = sq[r][h*16 + d];
            sw = fmaf(q, W5w[h*16 + d], sw);
            sb = fmaf(q, W5b[h*16 + d], sb);
        }
        g_qw5[(row0 + r)*NH + h] = sw;
        g_qb5[(row0 + r)*NH + h] = sb;
    }
}

// ---------------------------------------------------------------------------
// Kernel 2: fused scores+exp + sum + attn*V(normalized) + residual + LN.
// One block per (b, TI=8 query rows). 512 threads. ~103 KB dynamic smem,
// launch_bounds(512,2) pins regs at 64 -> 2 blocks/SM.
// Masking via additive penalty: acc init includes (adj-1)*50, so masked
// entries give exp(-50+small) ~ 2e-22 (exact-enough zero, no branch/select).
// ---------------------------------------------------------------------------
#define SM_FLOATS (TI*NH*SCP + HH*TI + TI*NH + TI*NH + 32 + NSL*TI*HH + TI*HH)
#define SM_BYTES  (SM_FLOATS * 4)

__global__ __launch_bounds__(512, 2)
void attn_kernel(const float* __restrict__ x,
                 const int*   __restrict__ adj,
                 const float* __restrict__ ef,
                 const float* __restrict__ lng,
                 const float* __restrict__ lnb,
                 float* __restrict__ out)
{
    extern __shared__ float smem[];
    float* s_sc  = smem;                   // [TI*NH][SCP] exp(scores)
    float* s_qt  = s_sc + TI*NH*SCP;       // [HH][TI]  Q transposed
    float* s_qw  = s_qt + HH*TI;           // TI*NH
    float* s_qb  = s_qw + TI*NH;           // TI*NH
    float* s_inv = s_qb + TI*NH;           // 32: 1/sum per unit
    float* s_red = s_inv + 32;             // [NSL][TI*HH]
    float* s_y   = s_red + NSL*TI*HH;      // TI*HH

    const int tid = threadIdx.x;                  // 0..511
    const int b   = blockIdx.x / (NN / TI);
    const int i0  = (blockIdx.x % (NN / TI)) * TI;

    // Stage Q transposed: s_qt[hd][i]
    {
        const int i = tid >> 6, hd = tid & 63;
        s_qt[hd*TI + i] = g_Q[(b*NN + i0 + i)*HH + hd];
    }
    if (tid < TI*NH) {
        s_qw[tid] = g_qw5[(b*NN + i0)*NH + tid];
        s_qb[tid] = g_qb5[(b*NN + i0)*NH + tid];
    }
    __syncthreads();

    // ---- Phase 1: scores + exp. thread = (head-pair hp, j-pair jp). ----
    {
        const int hp = tid >> 8;            // 0/1: heads {0,1} or {2,3}
        const int jp = tid & 255;
        const int j0 = jp * 2;
        const float* KtB = &g_Kt[(long)b*HH*NN];

        // acc[hh][jj][i], initialized with edge term + adjacency penalty
        float acc[2][2][TI];
        #pragma unroll
        for (int i = 0; i < TI; i++) {
            const long base = (long)(b*NN + i0 + i)*NN + j0;
            const float2 e2 = *(const float2*)&ef[base];
            const int2  a2 = *(const int2*)&adj[base];
            const float pen0 = fmaf((float)a2.x, 50.f, -50.f);  // 0 or -50
            const float pen1 = fmaf((float)a2.y, 50.f, -50.f);
            const float2 qw = *(const float2*)&s_qw[i*NH + hp*2];
            const float2 qb = *(const float2*)&s_qb[i*NH + hp*2];
            acc[0][0][i] = fmaf(e2.x, qw.x, qb.x + pen0);
            acc[0][1][i] = fmaf(e2.y, qw.x, qb.x + pen1);
            acc[1][0][i] = fmaf(e2.x, qw.y, qb.y + pen0);
            acc[1][1][i] = fmaf(e2.y, qw.y, qb.y + pen1);
        }

        #pragma unroll
        for (int hh = 0; hh < 2; hh++) {
            const int h = hp*2 + hh;
            #pragma unroll
            for (int d = 0; d < DD; d++) {
                const int hd = h*DD + d;
                const float2 kt = *(const float2*)&KtB[hd*NN + j0];  // LDG.64
                const float4 qa = *(const float4*)&s_qt[hd*TI];      // bcast
                const float4 qc = *(const float4*)&s_qt[hd*TI + 4];
                acc[hh][0][0] = fmaf(qa.x, kt.x, acc[hh][0][0]);
                acc[hh][1][0] = fmaf(qa.x, kt.y, acc[hh][1][0]);
                acc[hh][0][1] = fmaf(qa.y, kt.x, acc[hh][0][1]);
                acc[hh][1][1] = fmaf(qa.y, kt.y, acc[hh][1][1]);
                acc[hh][0][2] = fmaf(qa.z, kt.x, acc[hh][0][2]);
                acc[hh][1][2] = fmaf(qa.z, kt.y, acc[hh][1][2]);
                acc[hh][0][3] = fmaf(qa.w, kt.x, acc[hh][0][3]);
                acc[hh][1][3] = fmaf(qa.w, kt.y, acc[hh][1][3]);
                acc[hh][0][4] = fmaf(qc.x, kt.x, acc[hh][0][4]);
                acc[hh][1][4] = fmaf(qc.x, kt.y, acc[hh][1][4]);
                acc[hh][0][5] = fmaf(qc.y, kt.x, acc[hh][0][5]);
                acc[hh][1][5] = fmaf(qc.y, kt.y, acc[hh][1][5]);
                acc[hh][0][6] = fmaf(qc.z, kt.x, acc[hh][0][6]);
                acc[hh][1][6] = fmaf(qc.z, kt.y, acc[hh][1][6]);
                acc[hh][0][7] = fmaf(qc.w, kt.x, acc[hh][0][7]);
                acc[hh][1][7] = fmaf(qc.w, kt.y, acc[hh][1][7]);
            }
        }

        #pragma unroll
        for (int i = 0; i < TI; i++) {
            #pragma unroll
            for (int hh = 0; hh < 2; hh++) {
                const int h = hp*2 + hh;
                float2 e;
                e.x = __expf(acc[hh][0][i]);
                e.y = __expf(acc[hh][1][i]);
                *(float2*)&s_sc[(i*NH + h)*SCP + j0] = e;
            }
        }
    }
    __syncthreads();

    // ---- Phase 2: per-unit sum -> 1/sum. warp w does units w, w+16. ----
    {
        const int w = tid >> 5, lane = tid & 31;
        #pragma unroll
        for (int uu = 0; uu < 2; uu++) {
            const int u = w + 16*uu;
            const float* row = &s_sc[u*SCP];
            float sum = 0.f;
            #pragma unroll
            for (int k = 0; k < 16; k++) sum += row[lane + 32*k];
            #pragma unroll
            for (int o = 16; o; o >>= 1) sum += __shfl_xor_sync(0xffffffffu, sum, o);
            if (lane == 0) s_inv[u] = 1.f / sum;
        }
    }
    __syncthreads();

    // ---- Phase 3: msg = (E @ V) * inv. thread = (32-j slice, c-pair). ----
    {
        const int slice = tid >> 5;   // 0..15, 32 j each
        const int cp    = tid & 31;
        const int c0    = cp * 2;     // output cols c0, c0+1
        const int h     = cp >> 3;    // head of both cols
        float acc0[TI], acc1[TI];
        #pragma unroll
        for (int i = 0; i < TI; i++) { acc0[i] = 0.f; acc1[i] = 0.f; }
        const float* Vb = &g_V[(long)b*NN*HH];
        #pragma unroll
        for (int js = 0; js < 8; js++) {
            const int jx = slice*32 + js*4;
            const float2 v0 = *(const float2*)&Vb[(jx+0)*HH + c0];
            const float2 v1 = *(const float2*)&Vb[(jx+1)*HH + c0];
            const float2 v2 = *(const float2*)&Vb[(jx+2)*HH + c0];
            const float2 v3 = *(const float2*)&Vb[(jx+3)*HH + c0];
            #pragma unroll
            for (int i = 0; i < TI; i++) {
                const float4 p = *(const float4*)&s_sc[(i*NH + h)*SCP + jx];
                acc0[i] = fmaf(p.x, v0.x, acc0[i]);
                acc1[i] = fmaf(p.x, v0.y, acc1[i]);
                acc0[i] = fmaf(p.y, v1.x, acc0[i]);
                acc1[i] = fmaf(p.y, v1.y, acc1[i]);
                acc0[i] = fmaf(p.z, v2.x, acc0[i]);
                acc1[i] = fmaf(p.z, v2.y, acc1[i]);
                acc0[i] = fmaf(p.w, v3.x, acc0[i]);
                acc1[i] = fmaf(p.w, v3.y, acc1[i]);
            }
        }
        #pragma unroll
        for (int i = 0; i < TI; i++) {
            const float inv = s_inv[i*NH + h];
            float2 r; r.x = acc0[i]*inv; r.y = acc1[i]*inv;
            *(float2*)&s_red[(slice*TI + i)*HH + c0] = r;
        }
    }
    __syncthreads();

    // ---- Phase 3b: reduce slices + residual. tid covers TI*HH = 512. ----
    {
        const int i = tid >> 6, c = tid & 63;
        float m = 0.f;
        #pragma unroll
        for (int s = 0; s < NSL; s++) m += s_red[(s*TI + i)*HH + c];
        const long r = (long)(b*NN + i0 + i)*HH + c;
        s_y[i*HH + c] = x[r] + g_T[r] + m;
    }
    __syncthreads();

    // ---- Phase 4: LayerNorm. warp w handles row i=w (TI*32 = 256 threads). -
    if (tid < TI*32) {
        const int i = tid >> 5, l = tid & 31;
        const float y0 = s_y[i*HH + l];
        const float y1 = s_y[i*HH + l + 32];
        float s  = y0 + y1;
        float sq = y0*y0 + y1*y1;
        #pragma unroll
        for (int o = 16; o; o >>= 1) {
            s  += __shfl_xor_sync(0xffffffffu, s,  o);
            sq += __shfl_xor_sync(0xffffffffu, sq, o);
        }
        const float mean = s * (1.f/64.f);
        const float var  = sq * (1.f/64.f) - mean*mean;
        const float rs   = rsqrtf(var + LN_EPS);
        float* op = &out[(long)(b*NN + i0 + i)*HH];
        op[l]      = (y0 - mean)*rs*lng[l]      + lnb[l];
        op[l + 32] = (y1 - mean)*rs*lng[l + 32] + lnb[l + 32];
    }
}

// ---------------------------------------------------------------------------
extern "C" void kernel_launch(void* const* d_in, const int* in_sizes, int n_in,
                              void* d_out, int out_size)
{
    const float* x   = (const float*)d_in[0];
    const int*   adj = (const int*)  d_in[1];
    const float* ef  = (const float*)d_in[2];
    const float* W1w = (const float*)d_in[3];
    const float* W1b = (const float*)d_in[4];
    const float* W2w = (const float*)d_in[5];
    const float* W2b = (const float*)d_in[6];
    const float* W3w = (const float*)d_in[7];
    const float* W3b = (const float*)d_in[8];
    const float* W4w = (const float*)d_in[9];
    const float* W4b = (const float*)d_in[10];
    const float* W5w = (const float*)d_in[11];
    const float* W5b = (const float*)d_in[12];
    const float* lng = (const float*)d_in[13];
    const float* lnb = (const float*)d_in[14];

    cudaFuncSetAttribute(attn_kernel,
                         cudaFuncAttributeMaxDynamicSharedMemorySize, SM_BYTES);

    proj_kernel<<<BB*NN/8, 256>>>(x, W1w, W1b, W2w, W2b, W3w, W3b,
                                  W4w, W4b, W5w, W5b);
    attn_kernel<<<BB*NN/TI, 512, SM_BYTES>>>(x, adj, ef, lng, lnb,
                                             (float*)d_out);
}

// round 16
// speedup vs baseline: 1.4340x; 1.0026x over previous
#include <cuda_runtime.h>
#include <math.h>

#define BB 4
#define NN 512
#define SCP (NN + 4)     // padded score-row stride (bank-conflict-free over h)
#define HH 64
#define NH 4
#define DD 16
#define SCALE 0.25f      // 1/sqrt(16)
#define LN_EPS 1e-5f
#define TI 8             // query rows per block
#define NSL 16           // j-slices in phase 3
#define GRIDN (BB*NN/TI) // 256 blocks

// Cross-block scratch (only K^t and V are consumed by other blocks)
__device__ float g_Kt[BB*HH*NN];   // K transposed: [b][hd][j]
__device__ float g_V [BB*NN*HH];
// Monotonic barrier ticket counter (never reset -> graph-replay safe)
__device__ unsigned int g_cnt;

// ---------------------------------------------------------------------------
// ONE fused kernel: projections for own 8 rows -> device barrier ->
// scores+exp -> softmax-sum -> attn*V -> residual -> LayerNorm.
// 256 blocks x 512 threads, ~105 KB smem, launch_bounds(512,2) -> 64 regs,
// 2 blocks/SM -> 296-slot residency >= 256 blocks (barrier is safe).
// ---------------------------------------------------------------------------
#define SM_FLOATS (TI*NH*SCP + HH*TI + TI*NH + TI*NH + 32 + NSL*TI*HH + TI*HH + TI*HH)
#define SM_BYTES  (SM_FLOATS * 4)

__global__ __launch_bounds__(512, 2)
void fused_kernel(const float* __restrict__ x,
                  const int*   __restrict__ adj,
                  const float* __restrict__ ef,
                  const float* __restrict__ W1w, const float* __restrict__ W1b,
                  const float* __restrict__ W2w, const float* __restrict__ W2b,
                  const float* __restrict__ W3w, const float* __restrict__ W3b,
                  const float* __restrict__ W4w, const float* __restrict__ W4b,
                  const float* __restrict__ W5w, const float* __restrict__ W5b,
                  const float* __restrict__ lng,
                  const float* __restrict__ lnb,
                  float* __restrict__ out)
{
    extern __shared__ float smem[];
    float* s_sc  = smem;                   // [TI*NH][SCP] exp(scores)
    float* s_qt  = s_sc + TI*NH*SCP;       // [HH][TI]  Q transposed (scaled)
    float* s_qw  = s_qt + HH*TI;           // TI*NH (scaled)
    float* s_qb  = s_qw + TI*NH;           // TI*NH (scaled)
    float* s_inv = s_qb + TI*NH;           // 32: 1/sum per unit
    float* s_red = s_inv + 32;             // [NSL][TI*HH]
    float* s_y   = s_red + NSL*TI*HH;      // TI*HH
    float* s_T   = s_y + TI*HH;            // TI*HH  (self-transform, block-local)
    float* sxp   = s_sc;                   // alias: [8][64] x staging (pre-phase1)

    const int tid  = threadIdx.x;          // 0..511
    const int bid  = blockIdx.x;
    const int row0 = bid * TI;             // global row base (== b*NN + i0)
    const int b    = bid >> 6;
    const int i0   = (bid & 63) * TI;

    // ================= Part A: projections for own 8 rows =================
    {
        const int t = tid & 63;
        sxp[(tid >> 6)*64 + t] = x[(row0 + (tid >> 6))*HH + t];
        __syncthreads();

        const int g4  = tid >> 7;          // 0:T 1:V 2:Q 3:K
        const int sub = (tid >> 6) & 1;    // row half: rows sub*4..sub*4+3
        const float* Ww = (g4 == 0) ? W1w : (g4 == 1) ? W2w : (g4 == 2) ? W3w : W4w;
        const float* Wb = (g4 == 0) ? W1b : (g4 == 1) ? W2b : (g4 == 2) ? W3b : W4b;
        const float* xs = &sxp[sub*4*64];

        float a0 = 0.f, a1 = 0.f, a2 = 0.f, a3 = 0.f;
        #pragma unroll 8
        for (int k = 0; k < 64; k++) {
            const float w = Ww[k*64 + t];
            a0 = fmaf(xs[0*64 + k], w, a0);
            a1 = fmaf(xs[1*64 + k], w, a1);
            a2 = fmaf(xs[2*64 + k], w, a2);
            a3 = fmaf(xs[3*64 + k], w, a3);
        }
        const float bb = Wb[t];
        a0 += bb; a1 += bb; a2 += bb; a3 += bb;
        const int r0 = sub*4;

        if (g4 == 0) {                     // self-transform -> smem only
            s_T[(r0+0)*HH + t] = a0;
            s_T[(r0+1)*HH + t] = a1;
            s_T[(r0+2)*HH + t] = a2;
            s_T[(r0+3)*HH + t] = a3;
        } else if (g4 == 1) {              // V -> global (cross-block)
            g_V[(row0 + r0 + 0)*HH + t] = a0;
            g_V[(row0 + r0 + 1)*HH + t] = a1;
            g_V[(row0 + r0 + 2)*HH + t] = a2;
            g_V[(row0 + r0 + 3)*HH + t] = a3;
        } else if (g4 == 2) {              // Q (scaled) -> smem transposed
            s_qt[t*TI + r0 + 0] = a0 * SCALE;
            s_qt[t*TI + r0 + 1] = a1 * SCALE;
            s_qt[t*TI + r0 + 2] = a2 * SCALE;
            s_qt[t*TI + r0 + 3] = a3 * SCALE;
        } else {                           // K transposed -> global
            const int bq = row0 >> 9;
            const int n0 = (row0 & (NN - 1)) + r0;
            *(float4*)&g_Kt[((long)bq*HH + t)*NN + n0] =
                make_float4(a0, a1, a2, a3);
        }
        __syncthreads();

        // qw5/qb5 from scaled Q in s_qt: 32 (r,h) pairs
        if (tid < 32) {
            const int r = tid >> 2, h = tid & 3;
            float sw = 0.f, sb = 0.f;
            #pragma unroll
            for (int d = 0; d < 16; d++) {
                const float q = s_qt[(h*16 + d)*TI + r];
                sw = fmaf(q, W5w[h*16 + d], sw);
                sb = fmaf(q, W5b[h*16 + d], sb);
            }
            s_qw[r*NH + h] = sw;
            s_qb[r*NH + h] = sb;
        }
    }

    // ================= Device-wide barrier (monotonic epoch) ==============
    __threadfence();
    __syncthreads();
    if (tid == 0) {
        const unsigned int ticket = atomicAdd(&g_cnt, 1u);
        const unsigned int target = (ticket / GRIDN + 1u) * GRIDN;
        while (atomicAdd(&g_cnt, 0u) < target) { }
    }
    __syncthreads();
    __threadfence();

    // ================= Phase 1: scores + exp =================
    {
        const int hp = tid >> 8;            // 0/1: heads {0,1} or {2,3}
        const int jp = tid & 255;
        const int j0 = jp * 2;
        const float* KtB = &g_Kt[(long)b*HH*NN];

        float acc[2][2][TI];
        #pragma unroll
        for (int i = 0; i < TI; i++) {
            const long base = (long)(b*NN + i0 + i)*NN + j0;
            const float2 e2 = *(const float2*)&ef[base];
            const int2  a2 = *(const int2*)&adj[base];
            const float pen0 = fmaf((float)a2.x, 50.f, -50.f);  // 0 or -50
            const float pen1 = fmaf((float)a2.y, 50.f, -50.f);
            const float2 qw = *(const float2*)&s_qw[i*NH + hp*2];
            const float2 qb = *(const float2*)&s_qb[i*NH + hp*2];
            acc[0][0][i] = fmaf(e2.x, qw.x, qb.x + pen0);
            acc[0][1][i] = fmaf(e2.y, qw.x, qb.x + pen1);
            acc[1][0][i] = fmaf(e2.x, qw.y, qb.y + pen0);
            acc[1][1][i] = fmaf(e2.y, qw.y, qb.y + pen1);
        }

        #pragma unroll
        for (int hh = 0; hh < 2; hh++) {
            const int h = hp*2 + hh;
            #pragma unroll
            for (int d = 0; d < DD; d++) {
                const int hd = h*DD + d;
                const float2 kt = *(const float2*)&KtB[hd*NN + j0];  // LDG.64
                const float4 qa = *(const float4*)&s_qt[hd*TI];      // bcast
                const float4 qc = *(const float4*)&s_qt[hd*TI + 4];
                acc[hh][0][0] = fmaf(qa.x, kt.x, acc[hh][0][0]);
                acc[hh][1][0] = fmaf(qa.x, kt.y, acc[hh][1][0]);
                acc[hh][0][1] = fmaf(qa.y, kt.x, acc[hh][0][1]);
                acc[hh][1][1] = fmaf(qa.y, kt.y, acc[hh][1][1]);
                acc[hh][0][2] = fmaf(qa.z, kt.x, acc[hh][0][2]);
                acc[hh][1][2] = fmaf(qa.z, kt.y, acc[hh][1][2]);
                acc[hh][0][3] = fmaf(qa.w, kt.x, acc[hh][0][3]);
                acc[hh][1][3] = fmaf(qa.w, kt.y, acc[hh][1][3]);
                acc[hh][0][4] = fmaf(qc.x, kt.x, acc[hh][0][4]);
                acc[hh][1][4] = fmaf(qc.x, kt.y, acc[hh][1][4]);
                acc[hh][0][5] = fmaf(qc.y, kt.x, acc[hh][0][5]);
                acc[hh][1][5] = fmaf(qc.y, kt.y, acc[hh][1][5]);
                acc[hh][0][6] = fmaf(qc.z, kt.x, acc[hh][0][6]);
                acc[hh][1][6] = fmaf(qc.z, kt.y, acc[hh][1][6]);
                acc[hh][0][7] = fmaf(qc.w, kt.x, acc[hh][0][7]);
                acc[hh][1][7] = fmaf(qc.w, kt.y, acc[hh][1][7]);
            }
        }

        #pragma unroll
        for (int i = 0; i < TI; i++) {
            #pragma unroll
            for (int hh = 0; hh < 2; hh++) {
                const int h = hp*2 + hh;
                float2 e;
                e.x = __expf(acc[hh][0][i]);
                e.y = __expf(acc[hh][1][i]);
                *(float2*)&s_sc[(i*NH + h)*SCP + j0] = e;
            }
        }
    }
    __syncthreads();

    // ================= Phase 2: per-unit sum -> 1/sum =================
    {
        const int w = tid >> 5, lane = tid & 31;
        #pragma unroll
        for (int uu = 0; uu < 2; uu++) {
            const int u = w + 16*uu;
            const float* row = &s_sc[u*SCP];
            float sum = 0.f;
            #pragma unroll
            for (int k = 0; k < 16; k++) sum += row[lane + 32*k];
            #pragma unroll
            for (int o = 16; o; o >>= 1) sum += __shfl_xor_sync(0xffffffffu, sum, o);
            if (lane == 0) s_inv[u] = 1.f / sum;
        }
    }
    __syncthreads();

    // ================= Phase 3: msg = (E @ V) * inv =================
    {
        const int slice = tid >> 5;   // 0..15, 32 j each
        const int cp    = tid & 31;
        const int c0    = cp * 2;     // output cols c0, c0+1
        const int h     = cp >> 3;
        float acc0[TI], acc1[TI];
        #pragma unroll
        for (int i = 0; i < TI; i++) { acc0[i] = 0.f; acc1[i] = 0.f; }
        const float* Vb = &g_V[(long)b*NN*HH];
        #pragma unroll
        for (int js = 0; js < 8; js++) {
            const int jx = slice*32 + js*4;
            const float2 v0 = *(const float2*)&Vb[(jx+0)*HH + c0];
            const float2 v1 = *(const float2*)&Vb[(jx+1)*HH + c0];
            const float2 v2 = *(const float2*)&Vb[(jx+2)*HH + c0];
            const float2 v3 = *(const float2*)&Vb[(jx+3)*HH + c0];
            #pragma unroll
            for (int i = 0; i < TI; i++) {
                const float4 p = *(const float4*)&s_sc[(i*NH + h)*SCP + jx];
                acc0[i] = fmaf(p.x, v0.x, acc0[i]);
                acc1[i] = fmaf(p.x, v0.y, acc1[i]);
                acc0[i] = fmaf(p.y, v1.x, acc0[i]);
                acc1[i] = fmaf(p.y, v1.y, acc1[i]);
                acc0[i] = fmaf(p.z, v2.x, acc0[i]);
                acc1[i] = fmaf(p.z, v2.y, acc1[i]);
                acc0[i] = fmaf(p.w, v3.x, acc0[i]);
                acc1[i] = fmaf(p.w, v3.y, acc1[i]);
            }
        }
        #pragma unroll
        for (int i = 0; i < TI; i++) {
            const float inv = s_inv[i*NH + h];
            float2 r; r.x = acc0[i]*inv; r.y = acc1[i]*inv;
            *(float2*)&s_red[(slice*TI + i)*HH + c0] = r;
        }
    }
    __syncthreads();

    // ================= Phase 3b: reduce + residual =================
    {
        const int i = tid >> 6, c = tid & 63;
        float m = 0.f;
        #pragma unroll
        for (int s = 0; s < NSL; s++) m += s_red[(s*TI + i)*HH + c];
        const long r = (long)(b*NN + i0 + i)*HH + c;
        s_y[i*HH + c] = x[r] + s_T[i*HH + c] + m;
    }
    __syncthreads();

    // ================= Phase 4: LayerNorm =================
    if (tid < TI*32) {
        const int i = tid >> 5, l = tid & 31;
        const float y0 = s_y[i*HH + l];
        const float y1 = s_y[i*HH + l + 32];
        float s  = y0 + y1;
        float sq = y0*y0 + y1*y1;
        #pragma unroll
        for (int o = 16; o; o >>= 1) {
            s  += __shfl_xor_sync(0xffffffffu, s,  o);
            sq += __shfl_xor_sync(0xffffffffu, sq, o);
        }
        const float mean = s * (1.f/64.f);
        const float var  = sq * (1.f/64.f) - mean*mean;
        const float rs   = rsqrtf(var + LN_EPS);
        float* op = &out[(long)(b*NN + i0 + i)*HH];
        op[l]      = (y0 - mean)*rs*lng[l]      + lnb[l];
        op[l + 32] = (y1 - mean)*rs*lng[l + 32] + lnb[l + 32];
    }
}

// ---------------------------------------------------------------------------
extern "C" void kernel_launch(void* const* d_in, const int* in_sizes, int n_in,
                              void* d_out, int out_size)
{
    const float* x   = (const float*)d_in[0];
    const int*   adj = (const int*)  d_in[1];
    const float* ef  = (const float*)d_in[2];
    const float* W1w = (const float*)d_in[3];
    const float* W1b = (const float*)d_in[4];
    const float* W2w = (const float*)d_in[5];
    const float* W2b = (const float*)d_in[6];
    const float* W3w = (const float*)d_in[7];
    const float* W3b = (const float*)d_in[8];
    const float* W4w = (const float*)d_in[9];
    const float* W4b = (const float*)d_in[10];
    const float* W5w = (const float*)d_in[11];
    const float* W5b = (const float*)d_in[12];
    const float* lng = (const float*)d_in[13];
    const float* lnb = (const float*)d_in[14];

    cudaFuncSetAttribute(fused_kernel,
                         cudaFuncAttributeMaxDynamicSharedMemorySize, SM_BYTES);

    fused_kernel<<<GRIDN, 512, SM_BYTES>>>(x, adj, ef,
                                           W1w, W1b, W2w, W2b, W3w, W3b,
                                           W4w, W4b, W5w, W5b,
                                           lng, lnb, (float*)d_out);
}

// round 17
// speedup vs baseline: 1.5364x; 1.0714x over previous
#include <cuda_runtime.h>
#include <math.h>

#define BB 4
#define NN 512
#define SCP (NN + 4)     // padded score-row stride (bank-conflict-free over h)
#define HH 64
#define NH 4
#define DD 16
#define SCALE 0.25f      // 1/sqrt(16)
#define LN_EPS 1e-5f
#define TI 8             // query rows per block
#define NSL 16           // j-slices in phase 3
#define GRIDN (BB*NN/TI) // 256 blocks
#define BPB  (NN/TI)     // 64 blocks per batch

// Cross-block scratch (only K^t and V are consumed by other blocks)
__device__ float g_Kt[BB*HH*NN];   // K transposed: [b][hd][j]
__device__ float g_V [BB*NN*HH];
// Monotonic per-batch barrier counters (never reset -> graph-replay safe)
__device__ unsigned int g_cnt[BB];

// ---------------------------------------------------------------------------
// ONE fused kernel: projections for own 8 rows -> per-batch barrier
// (overlapped with ef/adj loads) -> scores+exp -> sum -> attn*V -> LN.
// 256 blocks x 512 threads, ~105 KB smem, launch_bounds(512,2) -> 64 regs.
// ---------------------------------------------------------------------------
#define SM_FLOATS (TI*NH*SCP + HH*TI + TI*NH + TI*NH + 32 + NSL*TI*HH + TI*HH + TI*HH)
#define SM_BYTES  (SM_FLOATS * 4)

__global__ __launch_bounds__(512, 2)
void fused_kernel(const float* __restrict__ x,
                  const int*   __restrict__ adj,
                  const float* __restrict__ ef,
                  const float* __restrict__ W1w, const float* __restrict__ W1b,
                  const float* __restrict__ W2w, const float* __restrict__ W2b,
                  const float* __restrict__ W3w, const float* __restrict__ W3b,
                  const float* __restrict__ W4w, const float* __restrict__ W4b,
                  const float* __restrict__ W5w, const float* __restrict__ W5b,
                  const float* __restrict__ lng,
                  const float* __restrict__ lnb,
                  float* __restrict__ out)
{
    extern __shared__ float smem[];
    float* s_sc  = smem;                   // [TI*NH][SCP] exp(scores)
    float* s_qt  = s_sc + TI*NH*SCP;       // [HH][TI]  Q transposed (scaled)
    float* s_qw  = s_qt + HH*TI;           // TI*NH (scaled)
    float* s_qb  = s_qw + TI*NH;           // TI*NH (scaled)
    float* s_inv = s_qb + TI*NH;           // 32: 1/sum per unit
    float* s_red = s_inv + 32;             // [NSL][TI*HH]
    float* s_y   = s_red + NSL*TI*HH;      // TI*HH
    float* s_T   = s_y + TI*HH;            // TI*HH  (self-transform, block-local)
    float* sxp   = s_sc;                   // alias: [8][64] x staging (pre-phase1)

    const int tid  = threadIdx.x;          // 0..511
    const int bid  = blockIdx.x;
    const int row0 = bid * TI;             // global row base (== b*NN + i0)
    const int b    = bid >> 6;
    const int i0   = (bid & 63) * TI;

    // ================= Part A: projections for own 8 rows =================
    {
        const int t = tid & 63;
        sxp[(tid >> 6)*64 + t] = x[(row0 + (tid >> 6))*HH + t];
        __syncthreads();

        const int g4  = tid >> 7;          // 0:T 1:V 2:Q 3:K
        const int sub = (tid >> 6) & 1;    // row half: rows sub*4..sub*4+3
        const float* Ww = (g4 == 0) ? W1w : (g4 == 1) ? W2w : (g4 == 2) ? W3w : W4w;
        const float* Wb = (g4 == 0) ? W1b : (g4 == 1) ? W2b : (g4 == 2) ? W3b : W4b;
        const float* xs = &sxp[sub*4*64];

        float a0 = 0.f, a1 = 0.f, a2 = 0.f, a3 = 0.f;
        #pragma unroll 8
        for (int k = 0; k < 64; k++) {
            const float w = Ww[k*64 + t];
            a0 = fmaf(xs[0*64 + k], w, a0);
            a1 = fmaf(xs[1*64 + k], w, a1);
            a2 = fmaf(xs[2*64 + k], w, a2);
            a3 = fmaf(xs[3*64 + k], w, a3);
        }
        const float bb = Wb[t];
        a0 += bb; a1 += bb; a2 += bb; a3 += bb;
        const int r0 = sub*4;

        if (g4 == 0) {                     // self-transform -> smem only
            s_T[(r0+0)*HH + t] = a0;
            s_T[(r0+1)*HH + t] = a1;
            s_T[(r0+2)*HH + t] = a2;
            s_T[(r0+3)*HH + t] = a3;
        } else if (g4 == 1) {              // V -> global (cross-block)
            g_V[(row0 + r0 + 0)*HH + t] = a0;
            g_V[(row0 + r0 + 1)*HH + t] = a1;
            g_V[(row0 + r0 + 2)*HH + t] = a2;
            g_V[(row0 + r0 + 3)*HH + t] = a3;
        } else if (g4 == 2) {              // Q (scaled) -> smem transposed
            s_qt[t*TI + r0 + 0] = a0 * SCALE;
            s_qt[t*TI + r0 + 1] = a1 * SCALE;
            s_qt[t*TI + r0 + 2] = a2 * SCALE;
            s_qt[t*TI + r0 + 3] = a3 * SCALE;
        } else {                           // K transposed -> global
            const int bq = row0 >> 9;
            const int n0 = (row0 & (NN - 1)) + r0;
            *(float4*)&g_Kt[((long)bq*HH + t)*NN + n0] =
                make_float4(a0, a1, a2, a3);
        }
        __syncthreads();

        // qw5/qb5 from scaled Q in s_qt: 32 (r,h) pairs
        if (tid < 32) {
            const int r = tid >> 2, h = tid & 3;
            float sw = 0.f, sb = 0.f;
            #pragma unroll
            for (int d = 0; d < 16; d++) {
                const float q = s_qt[(h*16 + d)*TI + r];
                sw = fmaf(q, W5w[h*16 + d], sw);
                sb = fmaf(q, W5b[h*16 + d], sb);
            }
            s_qw[r*NH + h] = sw;
            s_qb[r*NH + h] = sb;
        }
    }
    __threadfence();       // make own g_V / g_Kt writes visible
    __syncthreads();       // all warps done with Part A (and s_qw/s_qb ready)

    // ===== Barrier arrival (per-batch) — then overlap wait with ef/adj =====
    if (tid == 0) atomicAdd(&g_cnt[b], 1u);

    // ---- Phase 1 prologue (independent of other blocks): ef/adj + init ----
    const int hp = tid >> 8;            // 0/1: heads {0,1} or {2,3}
    const int jp = tid & 255;
    const int j0 = jp * 2;

    float acc[2][2][TI];
    #pragma unroll
    for (int i = 0; i < TI; i++) {
        const long base = (long)(b*NN + i0 + i)*NN + j0;
        const float2 e2 = *(const float2*)&ef[base];
        const int2  a2 = *(const int2*)&adj[base];
        const float pen0 = fmaf((float)a2.x, 50.f, -50.f);  // 0 or -50
        const float pen1 = fmaf((float)a2.y, 50.f, -50.f);
        const float2 qw = *(const float2*)&s_qw[i*NH + hp*2];
        const float2 qb = *(const float2*)&s_qb[i*NH + hp*2];
        acc[0][0][i] = fmaf(e2.x, qw.x, qb.x + pen0);
        acc[0][1][i] = fmaf(e2.y, qw.x, qb.x + pen1);
        acc[1][0][i] = fmaf(e2.x, qw.y, qb.y + pen0);
        acc[1][1][i] = fmaf(e2.y, qw.y, qb.y + pen1);
    }

    // ---- Barrier wait: only this batch's 64 blocks; poll via L2 load ----
    if (tid == 0) {
        // monotonic epoch: each replay adds 64 to g_cnt[b]
        unsigned int cur = __ldcg(&g_cnt[b]);
        // target = next multiple-of-64 boundary at or above our arrival epoch.
        // Our own arrival is included in cur's epoch; compute from first read:
        // all replays advance in lockstep, so round cur up to a 64 boundary.
        const unsigned int target = ((cur + BPB - 1) / BPB) * BPB < cur + 1
                                    ? ((cur / BPB) + 1) * BPB
                                    : ((cur + BPB - 1) / BPB) * BPB;
        while (__ldcg(&g_cnt[b]) < target) { }
    }
    __syncthreads();
    __threadfence();

    // ================= Phase 1 main: Q.K over Kt =================
    {
        const float* KtB = &g_Kt[(long)b*HH*NN];
        #pragma unroll
        for (int hh = 0; hh < 2; hh++) {
            const int h = hp*2 + hh;
            #pragma unroll
            for (int d = 0; d < DD; d++) {
                const int hd = h*DD + d;
                const float2 kt = *(const float2*)&KtB[hd*NN + j0];  // LDG.64
                const float4 qa = *(const float4*)&s_qt[hd*TI];      // bcast
                const float4 qc = *(const float4*)&s_qt[hd*TI + 4];
                acc[hh][0][0] = fmaf(qa.x, kt.x, acc[hh][0][0]);
                acc[hh][1][0] = fmaf(qa.x, kt.y, acc[hh][1][0]);
                acc[hh][0][1] = fmaf(qa.y, kt.x, acc[hh][0][1]);
                acc[hh][1][1] = fmaf(qa.y, kt.y, acc[hh][1][1]);
                acc[hh][0][2] = fmaf(qa.z, kt.x, acc[hh][0][2]);
                acc[hh][1][2] = fmaf(qa.z, kt.y, acc[hh][1][2]);
                acc[hh][0][3] = fmaf(qa.w, kt.x, acc[hh][0][3]);
                acc[hh][1][3] = fmaf(qa.w, kt.y, acc[hh][1][3]);
                acc[hh][0][4] = fmaf(qc.x, kt.x, acc[hh][0][4]);
                acc[hh][1][4] = fmaf(qc.x, kt.y, acc[hh][1][4]);
                acc[hh][0][5] = fmaf(qc.y, kt.x, acc[hh][0][5]);
                acc[hh][1][5] = fmaf(qc.y, kt.y, acc[hh][1][5]);
                acc[hh][0][6] = fmaf(qc.z, kt.x, acc[hh][0][6]);
                acc[hh][1][6] = fmaf(qc.z, kt.y, acc[hh][1][6]);
                acc[hh][0][7] = fmaf(qc.w, kt.x, acc[hh][0][7]);
                acc[hh][1][7] = fmaf(qc.w, kt.y, acc[hh][1][7]);
            }
        }
        #pragma unroll
        for (int i = 0; i < TI; i++) {
            #pragma unroll
            for (int hh = 0; hh < 2; hh++) {
                const int h = hp*2 + hh;
                float2 e;
                e.x = __expf(acc[hh][0][i]);
                e.y = __expf(acc[hh][1][i]);
                *(float2*)&s_sc[(i*NH + h)*SCP + j0] = e;
            }
        }
    }
    __syncthreads();

    // ================= Phase 2: per-unit sum -> 1/sum =================
    {
        const int w = tid >> 5, lane = tid & 31;
        #pragma unroll
        for (int uu = 0; uu < 2; uu++) {
            const int u = w + 16*uu;
            const float* row = &s_sc[u*SCP];
            float sum = 0.f;
            #pragma unroll
            for (int k = 0; k < 16; k++) sum += row[lane + 32*k];
            #pragma unroll
            for (int o = 16; o; o >>= 1) sum += __shfl_xor_sync(0xffffffffu, sum, o);
            if (lane == 0) s_inv[u] = 1.f / sum;
        }
    }
    __syncthreads();

    // ================= Phase 3: msg = (E @ V) * inv =================
    {
        const int slice = tid >> 5;   // 0..15, 32 j each
        const int cp    = tid & 31;
        const int c0    = cp * 2;     // output cols c0, c0+1
        const int h     = cp >> 3;
        float acc0[TI], acc1[TI];
        #pragma unroll
        for (int i = 0; i < TI; i++) { acc0[i] = 0.f; acc1[i] = 0.f; }
        const float* Vb = &g_V[(long)b*NN*HH];
        #pragma unroll
        for (int js = 0; js < 8; js++) {
            const int jx = slice*32 + js*4;
            const float2 v0 = *(const float2*)&Vb[(jx+0)*HH + c0];
            const float2 v1 = *(const float2*)&Vb[(jx+1)*HH + c0];
            const float2 v2 = *(const float2*)&Vb[(jx+2)*HH + c0];
            const float2 v3 = *(const float2*)&Vb[(jx+3)*HH + c0];
            #pragma unroll
            for (int i = 0; i < TI; i++) {
                const float4 p = *(const float4*)&s_sc[(i*NH + h)*SCP + jx];
                acc0[i] = fmaf(p.x, v0.x, acc0[i]);
                acc1[i] = fmaf(p.x, v0.y, acc1[i]);
                acc0[i] = fmaf(p.y, v1.x, acc0[i]);
                acc1[i] = fmaf(p.y, v1.y, acc1[i]);
                acc0[i] = fmaf(p.z, v2.x, acc0[i]);
                acc1[i] = fmaf(p.z, v2.y, acc1[i]);
                acc0[i] = fmaf(p.w, v3.x, acc0[i]);
                acc1[i] = fmaf(p.w, v3.y, acc1[i]);
            }
        }
        #pragma unroll
        for (int i = 0; i < TI; i++) {
            const float inv = s_inv[i*NH + h];
            float2 r; r.x = acc0[i]*inv; r.y = acc1[i]*inv;
            *(float2*)&s_red[(slice*TI + i)*HH + c0] = r;
        }
    }
    __syncthreads();

    // ================= Phase 3b: reduce + residual =================
    {
        const int i = tid >> 6, c = tid & 63;
        float m = 0.f;
        #pragma unroll
        for (int s = 0; s < NSL; s++) m += s_red[(s*TI + i)*HH + c];
        const long r = (long)(b*NN + i0 + i)*HH + c;
        s_y[i*HH + c] = x[r] + s_T[i*HH + c] + m;
    }
    __syncthreads();

    // ================= Phase 4: LayerNorm =================
    if (tid < TI*32) {
        const int i = tid >> 5, l = tid & 31;
        const float y0 = s_y[i*HH + l];
        const float y1 = s_y[i*HH + l + 32];
        float s  = y0 + y1;
        float sq = y0*y0 + y1*y1;
        #pragma unroll
        for (int o = 16; o; o >>= 1) {
            s  += __shfl_xor_sync(0xffffffffu, s,  o);
            sq += __shfl_xor_sync(0xffffffffu, sq, o);
        }
        const float mean = s * (1.f/64.f);
        const float var  = sq * (1.f/64.f) - mean*mean;
        const float rs   = rsqrtf(var + LN_EPS);
        float* op = &out[(long)(b*NN + i0 + i)*HH];
        op[l]      = (y0 - mean)*rs*lng[l]      + lnb[l];
        op[l + 32] = (y1 - mean)*rs*lng[l + 32] + lnb[l + 32];
    }
}

// ---------------------------------------------------------------------------
extern "C" void kernel_launch(void* const* d_in, const int* in_sizes, int n_in,
                              void* d_out, int out_size)
{
    const float* x   = (const float*)d_in[0];
    const int*   adj = (const int*)  d_in[1];
    const float* ef  = (const float*)d_in[2];
    const float* W1w = (const float*)d_in[3];
    const float* W1b = (const float*)d_in[4];
    const float* W2w = (const float*)d_in[5];
    const float* W2b = (const float*)d_in[6];
    const float* W3w = (const float*)d_in[7];
    const float* W3b = (const float*)d_in[8];
    const float* W4w = (const float*)d_in[9];
    const float* W4b = (const float*)d_in[10];
    const float* W5w = (const float*)d_in[11];
    const float* W5b = (const float*)d_in[12];
    const float* lng = (const float*)d_in[13];
    const float* lnb = (const float*)d_in[14];

    cudaFuncSetAttribute(fused_kernel,
                         cudaFuncAttributeMaxDynamicSharedMemorySize, SM_BYTES);

    fused_kernel<<<GRIDN, 512, SM_BYTES>>>(x, adj, ef,
                                           W1w, W1b, W2w, W2b, W3w, W3b,
                                           W4w, W4b, W5w, W5b,
                                           lng, lnb, (float*)d_out);
}